// round 13
// baseline (speedup 1.0000x reference)
#include <cuda_runtime.h>
#include <cuda_bf16.h>
#include <mma.h>
#include <math.h>
#include <cstdint>

using namespace nvcuda;
typedef __nv_bfloat16 bf16;

#define C    8
#define L    512
#define NCF  (1024*8*2048)     // 16,777,216
#define LL   (512*512)

// ---- bf16 hi/lo scratch ----
__device__ bf16 g_c0h[NCF], g_c0l[NCF];
__device__ bf16 g_c1h[NCF], g_c1l[NCF];
__device__ bf16 g_c2h[NCF], g_c2l[NCF];
__device__ bf16 g_qh[NCF],  g_ql[NCF];
__device__ bf16 g_kh[NCF],  g_kl[NCF];
__device__ bf16 g_vh[NCF],  g_vl[NCF];
__device__ bf16 g_ah[NCF],  g_al[NCF];
__device__ bf16 g_ph[128*LL], g_pl[128*LL];   // exp'd softmax numerator, hi/lo
__device__ bf16 g_wh[4*C*65536], g_wl[4*C*65536];
__device__ float g_rsum[65536];

// ---- helpers ----
__device__ __forceinline__ uint32_t s2u(const void* p) {
    return (uint32_t)__cvta_generic_to_shared(p);
}
__device__ __forceinline__ void cpa16(uint32_t s, const void* g) {
    asm volatile("cp.async.cg.shared.global [%0], [%1], 16;" :: "r"(s), "l"(g));
}
#define CPCOMMIT() asm volatile("cp.async.commit_group;" ::: "memory")
#define CPWAIT()   asm volatile("cp.async.wait_group 0;" ::: "memory")
#define CPWAIT1()  asm volatile("cp.async.wait_group 1;" ::: "memory")

__device__ __forceinline__ void bsplit(float x, bf16& h, bf16& l) {
    h = __float2bfloat16(x);
    l = __float2bfloat16(x - __bfloat162float(h));
}
__device__ __forceinline__ uint32_t packbf2(bf16 a, bf16 b) {
    __nv_bfloat162 t; t.x = a; t.y = b;
    return *(uint32_t*)&t;
}
__device__ __forceinline__ void pack8(const float* v, uint4& H, uint4& Lo) {
    bf16 h[8], l[8];
    #pragma unroll
    for (int i = 0; i < 8; i++) bsplit(v[i], h[i], l[i]);
    H  = make_uint4(packbf2(h[0],h[1]), packbf2(h[2],h[3]), packbf2(h[4],h[5]), packbf2(h[6],h[7]));
    Lo = make_uint4(packbf2(l[0],l[1]), packbf2(l[2],l[3]), packbf2(l[4],l[5]), packbf2(l[6],l[7]));
}

typedef wmma::fragment<wmma::accumulator, 16, 16, 16, float> AccFrag;

// stage layouts (bytes), per stage:
//  qk  (40960): Qh 0  Ql 10240  Kh 20480  Kl 30720   [K-major 128x40, ldm 40]
//  qkv (37888): Wh 0  Wl 10240  ATh 20480 ATl 29184  [AT: 32x136, ldm 136]
//  pv  (37888): Ph 0  Pl 10240  Vh 20480  Vl 29184   [V: k x d, ldm 136]

// A row_major K-major (ldm 40); B col_major K-major (ldm 40)
__device__ __forceinline__ void mma_rAcB(const char* buf, int wm, int wn, AccFrag (&acc)[4][2]) {
    const bf16* Ah = (const bf16*)(buf);
    const bf16* Al = (const bf16*)(buf + 10240);
    const bf16* Bh = (const bf16*)(buf + 20480);
    const bf16* Bl = (const bf16*)(buf + 30720);
    #pragma unroll
    for (int ks = 0; ks < 2; ks++) {
        wmma::fragment<wmma::matrix_b, 16, 16, 16, bf16, wmma::col_major> bh[2], bl[2];
        #pragma unroll
        for (int j = 0; j < 2; j++) {
            int n_off = wn * 32 + j * 16;
            wmma::load_matrix_sync(bh[j], Bh + n_off * 40 + ks * 16, 40);
            wmma::load_matrix_sync(bl[j], Bl + n_off * 40 + ks * 16, 40);
        }
        #pragma unroll
        for (int i = 0; i < 4; i++) {
            int m_off = wm * 64 + i * 16;
            wmma::fragment<wmma::matrix_a, 16, 16, 16, bf16, wmma::row_major> ah, al;
            wmma::load_matrix_sync(ah, Ah + m_off * 40 + ks * 16, 40);
            wmma::load_matrix_sync(al, Al + m_off * 40 + ks * 16, 40);
            #pragma unroll
            for (int j = 0; j < 2; j++) {
                wmma::mma_sync(acc[i][j], ah, bh[j], acc[i][j]);
                wmma::mma_sync(acc[i][j], al, bh[j], acc[i][j]);
                wmma::mma_sync(acc[i][j], ah, bl[j], acc[i][j]);
            }
        }
    }
}

// A row_major K-major (ldm 40); B row_major [k][n] (ldm 136)
__device__ __forceinline__ void mma_rArB(const char* buf, int wm, int wn, AccFrag (&acc)[4][2]) {
    const bf16* Ah = (const bf16*)(buf);
    const bf16* Al = (const bf16*)(buf + 10240);
    const bf16* Bh = (const bf16*)(buf + 20480);
    const bf16* Bl = (const bf16*)(buf + 29184);
    #pragma unroll
    for (int ks = 0; ks < 2; ks++) {
        wmma::fragment<wmma::matrix_b, 16, 16, 16, bf16, wmma::row_major> bh[2], bl[2];
        #pragma unroll
        for (int j = 0; j < 2; j++) {
            int n_off = wn * 32 + j * 16;
            wmma::load_matrix_sync(bh[j], Bh + (ks * 16) * 136 + n_off, 136);
            wmma::load_matrix_sync(bl[j], Bl + (ks * 16) * 136 + n_off, 136);
        }
        #pragma unroll
        for (int i = 0; i < 4; i++) {
            int m_off = wm * 64 + i * 16;
            wmma::fragment<wmma::matrix_a, 16, 16, 16, bf16, wmma::row_major> ah, al;
            wmma::load_matrix_sync(ah, Ah + m_off * 40 + ks * 16, 40);
            wmma::load_matrix_sync(al, Al + m_off * 40 + ks * 16, 40);
            #pragma unroll
            for (int j = 0; j < 2; j++) {
                wmma::mma_sync(acc[i][j], ah, bh[j], acc[i][j]);
                wmma::mma_sync(acc[i][j], al, bh[j], acc[i][j]);
                wmma::mma_sync(acc[i][j], ah, bl[j], acc[i][j]);
            }
        }
    }
}

#define DECL_ACC() \
    AccFrag acc[4][2]; \
    _Pragma("unroll") for (int i_ = 0; i_ < 4; i_++) \
        _Pragma("unroll") for (int j_ = 0; j_ < 2; j_++) wmma::fill_fragment(acc[i_][j_], 0.0f);

#define EPI_TO_CS() \
    __syncthreads(); \
    { float* Cs_ = (float*)smem; \
      _Pragma("unroll") for (int i_ = 0; i_ < 4; i_++) \
        _Pragma("unroll") for (int j_ = 0; j_ < 2; j_++) \
          wmma::store_matrix_sync(Cs_ + (wm*64 + i_*16)*132 + wn*32 + j_*16, acc[i_][j_], 132, wmma::mem_row_major); } \
    __syncthreads();

// ============================================================
// conv3 + prep_w fused launch.
// blockIdx.x < 1024: conv blocks; >= 1024: weight-split blocks
// (which also zero g_rsum each call).
// ============================================================
__global__ void conv3_kernel(const float* __restrict__ x,
                             const float* __restrict__ wq,
                             const float* __restrict__ wk,
                             const float* __restrict__ wv,
                             const float* __restrict__ lwq, const float* __restrict__ lwk,
                             const float* __restrict__ lwv, const float* __restrict__ lwo) {
    __shared__ float xt[8*66*10];
    __shared__ float wsm[3*576];
    const int tid = threadIdx.x;

    if (blockIdx.x >= 1024) {
        int idx = (((blockIdx.x - 1024) * 4 + blockIdx.y)) * 256 + tid;   // 0 .. 2M-1
        if (idx < 65536) g_rsum[idx] = 0.0f;
        int t = idx >> 19, off = idx & 524287;
        const float* src = (t == 0) ? lwq : (t == 1) ? lwk : (t == 2) ? lwv : lwo;
        bf16 h, l;
        bsplit(src[off], h, l);
        g_wh[idx] = h; g_wl[idx] = l;
        return;
    }

    const int n  = blockIdx.x;
    const int y0 = blockIdx.y * 64;
    const int b  = n >> 9, l = n & 511;

    for (int i = tid; i < 576; i += 256) {
        wsm[i] = wq[i]; wsm[576 + i] = wk[i]; wsm[1152 + i] = wv[i];
    }
    for (int i = tid; i < 8*66*10; i += 256) {
        int ci = i / 660, rem = i % 660;
        int yy = rem / 10, xx = rem % 10;
        int y = y0 + yy - 1, xc = xx - 1;
        float v = 0.f;
        if (y >= 0 && y < 256 && xc >= 0 && xc < 8)
            v = x[(((size_t)(b*C + ci)*L + l)*256 + y)*8 + xc];
        xt[i] = v;
    }
    __syncthreads();

    const int yb = tid >> 3, w = tid & 7;
    float acc[2][24];
    #pragma unroll
    for (int r = 0; r < 2; r++)
        #pragma unroll
        for (int o = 0; o < 24; o++) acc[r][o] = 0.f;

    for (int ci = 0; ci < 8; ci++) {
        float xv[2][9];
        #pragma unroll
        for (int r = 0; r < 2; r++)
            #pragma unroll
            for (int ky = 0; ky < 3; ky++)
                #pragma unroll
                for (int kx = 0; kx < 3; kx++)
                    xv[r][ky*3 + kx] = xt[ci*660 + (yb + r*32 + ky)*10 + (w + kx)];
        #pragma unroll
        for (int o = 0; o < 24; o++) {
            int p = o >> 3, co = o & 7;
            const float* wp = &wsm[p*576 + (co*8 + ci)*9];
            #pragma unroll
            for (int k9 = 0; k9 < 9; k9++) {
                float ww = wp[k9];
                acc[0][o] += xv[0][k9] * ww;
                acc[1][o] += xv[1][k9] * ww;
            }
        }
    }
    #pragma unroll
    for (int p = 0; p < 3; p++) {
        bf16* oh = (p == 0) ? g_c0h : (p == 1) ? g_c1h : g_c2h;
        bf16* ol = (p == 0) ? g_c0l : (p == 1) ? g_c1l : g_c2l;
        #pragma unroll
        for (int co = 0; co < 8; co++)
            #pragma unroll
            for (int r = 0; r < 2; r++) {
                size_t off = (size_t)n*16384 + co*2048 + (size_t)(y0 + yb + r*32)*8 + w;
                bf16 hh, lv;
                bsplit(acc[r][p*8 + co], hh, lv);
                oh[off] = hh; ol[off] = lv;
            }
    }
}

// ============================================================
// qkv_wm: 3 projections, transposed: outT[g][m] = W[g][:].AT[:][m]
// 3-stage cp.async pipeline, coalesced A loads + epilogue.
// grid (64, 2, 24), block 256, 2 CTAs/SM.
// ============================================================
#define QKV_SMEM 113664
__global__ void __launch_bounds__(256, 2)
qkv_wm() {
    extern __shared__ __align__(16) char smem[];
    const uint32_t sb = s2u(smem);
    const int tid = threadIdx.x, wid = tid >> 5;
    const int wm = wid >> 2, wn = wid & 3;
    const int c = blockIdx.z & 7, proj = blockIdx.z >> 3;
    const int m0 = blockIdx.x * 128, g0 = blockIdx.y * 128, n0 = m0 >> 3;
    const bf16* Ah_g = (proj == 0) ? g_c0h : (proj == 1) ? g_c1h : g_c2h;
    const bf16* Al_g = (proj == 0) ? g_c0l : (proj == 1) ? g_c1l : g_c2l;
    const bf16* Wh_g = g_wh + (size_t)proj * 524288;
    const bf16* Wl_g = g_wl + (size_t)proj * 524288;
    bf16* Oh = (proj == 0) ? g_qh : (proj == 1) ? g_kh : g_vh;
    bf16* Ol = (proj == 0) ? g_ql : (proj == 1) ? g_kl : g_vl;

    DECL_ACC();

    // A chunk mapping: hr = ch&31 (fastest) -> consecutive lanes read
    // consecutive 16B groups along h (contiguous 512B per warp).
    #define QKVLD(s, kc) { \
        uint32_t sbase = sb + (s) * 37888; int k0 = (kc) * 32; \
        _Pragma("unroll") for (int i = 0; i < 2; i++) { \
            int ch = tid + i * 256; \
            int gr = ch >> 2, c4 = ch & 3; \
            size_t gb = (size_t)c * 65536 + (size_t)(g0 + gr) * 256 + k0 + c4 * 8; \
            cpa16(sbase + gr * 80 + c4 * 16,         Wh_g + gb); \
            cpa16(sbase + 10240 + gr * 80 + c4 * 16, Wl_g + gb); \
            int hr = ch & 31, nl = ch >> 5; \
            size_t ga = (size_t)(n0 + nl) * 16384 + c * 2048 + (size_t)(k0 + hr) * 8; \
            cpa16(sbase + 20480 + hr * 272 + nl * 16, Ah_g + ga); \
            cpa16(sbase + 29184 + hr * 272 + nl * 16, Al_g + ga); \
        } }

    QKVLD(0, 0); CPCOMMIT();
    QKVLD(1, 1); CPCOMMIT();
    for (int kc = 0; kc < 8; kc++) {
        if (kc == 7) { CPWAIT(); } else { CPWAIT1(); }
        __syncthreads();
        if (kc < 6) { QKVLD((kc + 2) % 3, kc + 2); CPCOMMIT(); }
        mma_rArB(smem + (kc % 3) * 37888, wm, wn, acc);
    }

    // Cs holds outT: row = g_rel, col = m_rel = (n-n0)*8 + w
    EPI_TO_CS();
    const float* Cs = (const float*)smem;
    #pragma unroll
    for (int it = 0; it < 8; it++) {
        int p = tid + it * 256;
        int nl = p >> 7, gr = p & 127;      // coalesced: consecutive tid -> consecutive g
        const float* src = Cs + gr * 132 + nl * 8;
        float4 v01 = *(const float4*)(src);
        float4 v23 = *(const float4*)(src + 4);
        float v[8] = {v01.x, v01.y, v01.z, v01.w, v23.x, v23.y, v23.z, v23.w};
        // fused RoPE: q/k projections, head-dims d = (g&31)*8 + w < 32
        int g = g0 + gr;
        if (proj < 2 && (g & 31) < 4) {
            int l = (n0 + nl) & 511;
            int jb = (g & 31) * 4;
            #pragma unroll
            for (int t = 0; t < 4; t++) {
                float invf = exp2f(-(float)(jb + t) * (13.287712379549449f / 16.0f));
                float sn, cn;
                sincosf((float)l * invf, &sn, &cn);
                float a = v[2*t], bq = v[2*t+1];
                v[2*t]   = a * cn - bq * sn;
                v[2*t+1] = bq * cn + a * sn;
            }
        }
        uint4 H, Lo;
        pack8(v, H, Lo);
        size_t e = (size_t)(n0 + nl) * 16384 + (size_t)c * 2048 + (size_t)g * 8;
        *(uint4*)(Oh + e) = H;
        *(uint4*)(Ol + e) = Lo;
    }
}

// ============================================================
// qk_wm: 2-stage pipeline; epilogue writes qk f32 AND softmax
// numerator P = exp(qk) as bf16 hi/lo + per-row atomic sums.
// grid (4, 4, 128), block 256, 2 CTAs/SM.
// ============================================================
#define QK_SMEM 81920
__global__ void __launch_bounds__(256, 2)
qk_wm(const float* __restrict__ prev, float* __restrict__ qk) {
    extern __shared__ __align__(16) char smem[];
    const uint32_t sb = s2u(smem);
    const int tid = threadIdx.x, wid = tid >> 5;
    const int wm = wid >> 2, wn = wid & 3;
    const int z = blockIdx.z;
    const int b = z >> 6, c = (z >> 3) & 7, nh = z & 7;
    const int l0 = blockIdx.y * 128, m0 = blockIdx.x * 128;
    const size_t coff = (size_t)c * 2048 + nh * 256;
    const size_t bL = (size_t)b * 512;

    DECL_ACC();

    #define QKLD(s, kc) { \
        uint32_t sbase = sb + (s) * 40960; int k0 = (kc) * 32; \
        _Pragma("unroll") for (int i = 0; i < 2; i++) { \
            int ch = tid + i * 256; \
            int r = ch >> 2, c4 = ch & 3; \
            uint32_t so = r * 80 + c4 * 16; \
            size_t ga = (bL + l0 + r) * 16384 + coff + k0 + c4 * 8; \
            size_t gb = (bL + m0 + r) * 16384 + coff + k0 + c4 * 8; \
            cpa16(sbase + so,         g_qh + ga); \
            cpa16(sbase + 10240 + so, g_ql + ga); \
            cpa16(sbase + 20480 + so, g_kh + gb); \
            cpa16(sbase + 30720 + so, g_kl + gb); \
        } }

    QKLD(0, 0); CPCOMMIT();
    for (int kc = 0; kc < 8; kc++) {
        CPWAIT(); __syncthreads();
        if (kc < 7) { QKLD((kc + 1) & 1, kc + 1); CPCOMMIT(); }
        mma_rAcB(smem + (kc & 1) * 40960, wm, wn, acc);
    }

    EPI_TO_CS();
    const float* Cs = (const float*)smem;
    const int col4 = (tid & 31) * 4;
    const int rb = tid >> 5;
    const int lane = tid & 31;
    #pragma unroll 4
    for (int jj = 0; jj < 16; jj++) {
        int r = rb + jj * 8;
        float4 cv = *(const float4*)(Cs + r * 132 + col4);
        size_t idx = (size_t)z * LL + (size_t)(l0 + r) * 512 + m0 + col4;
        float4 pv = *(const float4*)(prev + idx);
        float4 o;
        o.x = cv.x * 0.0625f + pv.x;
        o.y = cv.y * 0.0625f + pv.y;
        o.z = cv.z * 0.0625f + pv.z;
        o.w = cv.w * 0.0625f + pv.w;
        *(float4*)(qk + idx) = o;
        float e0 = __expf(o.x), e1 = __expf(o.y);
        float e2 = __expf(o.z), e3 = __expf(o.w);
        bf16 h0, lo0, h1, lo1, h2, lo2, h3, lo3;
        bsplit(e0, h0, lo0); bsplit(e1, h1, lo1);
        bsplit(e2, h2, lo2); bsplit(e3, h3, lo3);
        *(uint2*)(g_ph + idx) = make_uint2(packbf2(h0, h1), packbf2(h2, h3));
        *(uint2*)(g_pl + idx) = make_uint2(packbf2(lo0, lo1), packbf2(lo2, lo3));
        float s = e0 + e1 + e2 + e3;
        #pragma unroll
        for (int off = 16; off; off >>= 1) s += __shfl_xor_sync(~0u, s, off);
        if (lane == 0) atomicAdd(&g_rsum[z * 512 + l0 + r], s);
    }
}

// ============================================================
// pv_wm: pure 3-stage cp.async GEMM (P hi/lo, V hi/lo).
// grid (2, 4, 128), block 256, 2 CTAs/SM. K=512, 16 chunks.
// ============================================================
#define PV_SMEM 114688
__global__ void __launch_bounds__(256, 2)
pv_wm() {
    extern __shared__ __align__(16) char smem[];
    const uint32_t sb = s2u(smem);
    const int tid = threadIdx.x, wid = tid >> 5;
    const int wm = wid >> 2, wn = wid & 3;
    const int z = blockIdx.z;
    const int b = z >> 6, c = (z >> 3) & 7, nh = z & 7;
    const int l0 = blockIdx.y * 128, d0 = blockIdx.x * 128;
    const size_t coff = (size_t)c * 2048 + nh * 256;
    const size_t bL = (size_t)b * 512;
    float* rinv = (float*)(smem + 113664);
    if (tid < 128) rinv[tid] = 1.0f / g_rsum[z * 512 + l0 + tid];

    DECL_ACC();

    #define PVLD(s, kc) { \
        uint32_t sbase = sb + (s) * 37888; int k0 = (kc) * 32; \
        _Pragma("unroll") for (int i = 0; i < 2; i++) { \
            int ch = tid + i * 256; \
            int r = ch >> 2, c4 = ch & 3; \
            size_t gp = (size_t)z * LL + (size_t)(l0 + r) * 512 + k0 + c4 * 8; \
            cpa16(sbase + r * 80 + c4 * 16,         g_ph + gp); \
            cpa16(sbase + 10240 + r * 80 + c4 * 16, g_pl + gp); \
            int mr = ch >> 4, d8 = ch & 15; \
            size_t gv = (bL + k0 + mr) * 16384 + coff + d0 + d8 * 8; \
            cpa16(sbase + 20480 + mr * 272 + d8 * 16, g_vh + gv); \
            cpa16(sbase + 29184 + mr * 272 + d8 * 16, g_vl + gv); \
        } }

    PVLD(0, 0); CPCOMMIT();
    PVLD(1, 1); CPCOMMIT();
    for (int kc = 0; kc < 16; kc++) {
        if (kc == 15) { CPWAIT(); } else { CPWAIT1(); }
        __syncthreads();
        if (kc < 14) { PVLD((kc + 2) % 3, kc + 2); CPCOMMIT(); }
        mma_rArB(smem + (kc % 3) * 37888, wm, wn, acc);
    }

    EPI_TO_CS();
    const float* Cs = (const float*)smem;
    #pragma unroll
    for (int it = 0; it < 8; it++) {
        int r = (tid >> 4) + it * 16;
        int col8 = (tid & 15) * 8;
        float4 a1 = *(const float4*)(Cs + r * 132 + col8);
        float4 a2 = *(const float4*)(Cs + r * 132 + col8 + 4);
        float iv = rinv[r];
        float v[8] = {a1.x*iv, a1.y*iv, a1.z*iv, a1.w*iv, a2.x*iv, a2.y*iv, a2.z*iv, a2.w*iv};
        uint4 H, Lo;
        pack8(v, H, Lo);
        size_t e = (bL + l0 + r) * 16384 + coff + d0 + col8;
        *(uint4*)(g_ah + e) = H;
        *(uint4*)(g_al + e) = Lo;
    }
}

// ============================================================
// olin_wm: wo projection, transposed, 3-stage pipeline. -> f32 out.
// Coalesced A loads + epilogue.
// ============================================================
__global__ void __launch_bounds__(256, 2)
olin_wm(float* __restrict__ out) {
    extern __shared__ __align__(16) char smem[];
    const uint32_t sb = s2u(smem);
    const int tid = threadIdx.x, wid = tid >> 5;
    const int wm = wid >> 2, wn = wid & 3;
    const int c = blockIdx.z, m0 = blockIdx.x * 128, g0 = blockIdx.y * 128, n0 = m0 >> 3;
    const bf16* Wh_g = g_wh + (size_t)3 * 524288;
    const bf16* Wl_g = g_wl + (size_t)3 * 524288;

    DECL_ACC();

    #define OLD(s, kc) { \
        uint32_t sbase = sb + (s) * 37888; int k0 = (kc) * 32; \
        _Pragma("unroll") for (int i = 0; i < 2; i++) { \
            int ch = tid + i * 256; \
            int gr = ch >> 2, c4 = ch & 3; \
            size_t gb = (size_t)c * 65536 + (size_t)(g0 + gr) * 256 + k0 + c4 * 8; \
            cpa16(sbase + gr * 80 + c4 * 16,         Wh_g + gb); \
            cpa16(sbase + 10240 + gr * 80 + c4 * 16, Wl_g + gb); \
            int hr = ch & 31, nl = ch >> 5; \
            size_t ga = (size_t)(n0 + nl) * 16384 + c * 2048 + (size_t)(k0 + hr) * 8; \
            cpa16(sbase + 20480 + hr * 272 + nl * 16, g_ah + ga); \
            cpa16(sbase + 29184 + hr * 272 + nl * 16, g_al + ga); \
        } }

    OLD(0, 0); CPCOMMIT();
    OLD(1, 1); CPCOMMIT();
    for (int kc = 0; kc < 8; kc++) {
        if (kc == 7) { CPWAIT(); } else { CPWAIT1(); }
        __syncthreads();
        if (kc < 6) { OLD((kc + 2) % 3, kc + 2); CPCOMMIT(); }
        mma_rArB(smem + (kc % 3) * 37888, wm, wn, acc);
    }

    EPI_TO_CS();
    const float* Cs = (const float*)smem;
    #pragma unroll
    for (int it = 0; it < 8; it++) {
        int p = tid + it * 256;
        int nl = p >> 7, gr = p & 127;      // coalesced: consecutive tid -> consecutive g
        int n = n0 + nl, bb = n >> 9, l = n & 511;
        float4 o1 = *(const float4*)(Cs + gr * 132 + nl * 8);
        float4 o2 = *(const float4*)(Cs + gr * 132 + nl * 8 + 4);
        size_t e = ((size_t)(bb * 8 + c) * 512 + l) * 2048 + (size_t)(g0 + gr) * 8;
        *(float4*)(out + e)     = o1;
        *(float4*)(out + e + 4) = o2;
    }
}

// ============================================================
extern "C" void kernel_launch(void* const* d_in, const int* in_sizes, int n_in,
                              void* d_out, int out_size) {
    const float* x    = (const float*)d_in[0];
    const float* prev = (const float*)d_in[1];
    const float* cw_q = (const float*)d_in[2];
    const float* cw_k = (const float*)d_in[3];
    const float* cw_v = (const float*)d_in[4];
    const float* wq   = (const float*)d_in[5];
    const float* wk   = (const float*)d_in[6];
    const float* wv   = (const float*)d_in[7];
    const float* wo   = (const float*)d_in[8];
    float* out    = (float*)d_out;
    float* qk_out = out + (size_t)NCF;

    cudaFuncSetAttribute(qkv_wm,  cudaFuncAttributeMaxDynamicSharedMemorySize, QKV_SMEM);
    cudaFuncSetAttribute(olin_wm, cudaFuncAttributeMaxDynamicSharedMemorySize, QKV_SMEM);
    cudaFuncSetAttribute(qk_wm,   cudaFuncAttributeMaxDynamicSharedMemorySize, QK_SMEM);
    cudaFuncSetAttribute(pv_wm,   cudaFuncAttributeMaxDynamicSharedMemorySize, PV_SMEM);

    conv3_kernel<<<dim3(3072, 4), 256>>>(x, cw_q, cw_k, cw_v, wq, wk, wv, wo);
    qkv_wm<<<dim3(64, 2, 24), 256, QKV_SMEM>>>();
    qk_wm<<<dim3(4, 4, 128), 256, QK_SMEM>>>(prev, qk_out);
    pv_wm<<<dim3(2, 4, 128), 256, PV_SMEM>>>();
    olin_wm<<<dim3(64, 2, 8), 256, QKV_SMEM>>>(out);
}

// round 14
// speedup vs baseline: 1.4217x; 1.4217x over previous
#include <cuda_runtime.h>
#include <cuda_fp16.h>
#include <mma.h>
#include <math.h>
#include <cstdint>

using namespace nvcuda;
typedef __half hf;

#define C    8
#define L    512
#define NCF  (1024*8*2048)     // 16,777,216
#define LL   (512*512)

// ---- fp16 scratch: A-side tensors hi+lo, B-side hi only ----
__device__ hf g_c0[NCF], g_c1[NCF], g_c2[NCF];       // conv outs (B-side)
__device__ hf g_qh[NCF], g_ql[NCF];                  // q (A-side in qk)
__device__ hf g_k[NCF];                              // k (B-side)
__device__ hf g_v[NCF];                              // v (B-side)
__device__ hf g_a[NCF];                              // attn out (B-side in olin)
__device__ hf g_ph[128*LL], g_pl[128*LL];            // P (A-side in pv)
__device__ hf g_wh[4*C*65536], g_wl[4*C*65536];      // weights (A-side)
__device__ float g_rsum[65536];

// ---- helpers ----
__device__ __forceinline__ uint32_t s2u(const void* p) {
    return (uint32_t)__cvta_generic_to_shared(p);
}
__device__ __forceinline__ void cpa16(uint32_t s, const void* g) {
    asm volatile("cp.async.cg.shared.global [%0], [%1], 16;" :: "r"(s), "l"(g));
}
#define CPCOMMIT() asm volatile("cp.async.commit_group;" ::: "memory")
#define CPWAIT()   asm volatile("cp.async.wait_group 0;" ::: "memory")
#define CPWAIT1()  asm volatile("cp.async.wait_group 1;" ::: "memory")

__device__ __forceinline__ void hsplit(float x, hf& h, hf& l) {
    h = __float2half_rn(x);
    l = __float2half_rn(x - __half2float(h));
}
__device__ __forceinline__ uint32_t packh2(hf a, hf b) {
    __half2 t = __halves2half2(a, b);
    return *(uint32_t*)&t;
}
__device__ __forceinline__ void pack8hl(const float* v, uint4& H, uint4& Lo) {
    hf h[8], l[8];
    #pragma unroll
    for (int i = 0; i < 8; i++) hsplit(v[i], h[i], l[i]);
    H  = make_uint4(packh2(h[0],h[1]), packh2(h[2],h[3]), packh2(h[4],h[5]), packh2(h[6],h[7]));
    Lo = make_uint4(packh2(l[0],l[1]), packh2(l[2],l[3]), packh2(l[4],l[5]), packh2(l[6],l[7]));
}
__device__ __forceinline__ void pack8h(const float* v, uint4& H) {
    hf h[8];
    #pragma unroll
    for (int i = 0; i < 8; i++) h[i] = __float2half_rn(v[i]);
    H = make_uint4(packh2(h[0],h[1]), packh2(h[2],h[3]), packh2(h[4],h[5]), packh2(h[6],h[7]));
}

typedef wmma::fragment<wmma::accumulator, 16, 16, 16, float> AccFrag;

// stage layouts (bytes), per stage:
//  qk  (30720): Qh 0  Ql 10240  K 20480       [K-major 128x40 hf, ldm 40]
//  qkv (29184): Wh 0  Wl 10240  AT 20480      [AT: 32x136 hf, ldm 136]
//  pv  (29184): Ph 0  Pl 10240  V 20480       [V: 32x136 hf, ldm 136]

// A (hi/lo) row_major K-major ldm 40; B single col_major K-major ldm 40
__device__ __forceinline__ void mma2_rAcB(const char* buf, int wm, int wn, AccFrag (&acc)[4][2]) {
    const hf* Ah = (const hf*)(buf);
    const hf* Al = (const hf*)(buf + 10240);
    const hf* B  = (const hf*)(buf + 20480);
    #pragma unroll
    for (int ks = 0; ks < 2; ks++) {
        wmma::fragment<wmma::matrix_b, 16, 16, 16, hf, wmma::col_major> bf[2];
        #pragma unroll
        for (int j = 0; j < 2; j++)
            wmma::load_matrix_sync(bf[j], B + (wn * 32 + j * 16) * 40 + ks * 16, 40);
        #pragma unroll
        for (int i = 0; i < 4; i++) {
            int m_off = wm * 64 + i * 16;
            wmma::fragment<wmma::matrix_a, 16, 16, 16, hf, wmma::row_major> ah, al;
            wmma::load_matrix_sync(ah, Ah + m_off * 40 + ks * 16, 40);
            wmma::load_matrix_sync(al, Al + m_off * 40 + ks * 16, 40);
            #pragma unroll
            for (int j = 0; j < 2; j++) {
                wmma::mma_sync(acc[i][j], ah, bf[j], acc[i][j]);
                wmma::mma_sync(acc[i][j], al, bf[j], acc[i][j]);
            }
        }
    }
}

// A (hi/lo) row_major K-major ldm 40; B single row_major [k][n] ldm 136
__device__ __forceinline__ void mma2_rArB(const char* buf, int wm, int wn, AccFrag (&acc)[4][2]) {
    const hf* Ah = (const hf*)(buf);
    const hf* Al = (const hf*)(buf + 10240);
    const hf* B  = (const hf*)(buf + 20480);
    #pragma unroll
    for (int ks = 0; ks < 2; ks++) {
        wmma::fragment<wmma::matrix_b, 16, 16, 16, hf, wmma::row_major> bf[2];
        #pragma unroll
        for (int j = 0; j < 2; j++)
            wmma::load_matrix_sync(bf[j], B + (ks * 16) * 136 + wn * 32 + j * 16, 136);
        #pragma unroll
        for (int i = 0; i < 4; i++) {
            int m_off = wm * 64 + i * 16;
            wmma::fragment<wmma::matrix_a, 16, 16, 16, hf, wmma::row_major> ah, al;
            wmma::load_matrix_sync(ah, Ah + m_off * 40 + ks * 16, 40);
            wmma::load_matrix_sync(al, Al + m_off * 40 + ks * 16, 40);
            #pragma unroll
            for (int j = 0; j < 2; j++) {
                wmma::mma_sync(acc[i][j], ah, bf[j], acc[i][j]);
                wmma::mma_sync(acc[i][j], al, bf[j], acc[i][j]);
            }
        }
    }
}

#define DECL_ACC() \
    AccFrag acc[4][2]; \
    _Pragma("unroll") for (int i_ = 0; i_ < 4; i_++) \
        _Pragma("unroll") for (int j_ = 0; j_ < 2; j_++) wmma::fill_fragment(acc[i_][j_], 0.0f);

#define EPI_TO_CS() \
    __syncthreads(); \
    { float* Cs_ = (float*)smem; \
      _Pragma("unroll") for (int i_ = 0; i_ < 4; i_++) \
        _Pragma("unroll") for (int j_ = 0; j_ < 2; j_++) \
          wmma::store_matrix_sync(Cs_ + (wm*64 + i_*16)*132 + wn*32 + j_*16, acc[i_][j_], 132, wmma::mem_row_major); } \
    __syncthreads();

// ============================================================
// conv3 + prep_w fused launch.
// blockIdx.x < 1024: conv; >= 1024: weight-split + rsum zero.
// conv outputs stored single fp16 (B-side operands).
// ============================================================
__global__ void conv3_kernel(const float* __restrict__ x,
                             const float* __restrict__ wq,
                             const float* __restrict__ wk,
                             const float* __restrict__ wv,
                             const float* __restrict__ lwq, const float* __restrict__ lwk,
                             const float* __restrict__ lwv, const float* __restrict__ lwo) {
    __shared__ float xt[8*66*10];
    __shared__ float wsm[3*576];
    const int tid = threadIdx.x;

    if (blockIdx.x >= 1024) {
        int idx = (((blockIdx.x - 1024) * 4 + blockIdx.y)) * 256 + tid;   // 0 .. 2M-1
        if (idx < 65536) g_rsum[idx] = 0.0f;
        int t = idx >> 19, off = idx & 524287;
        const float* src = (t == 0) ? lwq : (t == 1) ? lwk : (t == 2) ? lwv : lwo;
        hf h, l;
        hsplit(src[off], h, l);
        g_wh[idx] = h; g_wl[idx] = l;
        return;
    }

    const int n  = blockIdx.x;
    const int y0 = blockIdx.y * 64;
    const int b  = n >> 9, l = n & 511;

    for (int i = tid; i < 576; i += 256) {
        wsm[i] = wq[i]; wsm[576 + i] = wk[i]; wsm[1152 + i] = wv[i];
    }
    for (int i = tid; i < 8*66*10; i += 256) {
        int ci = i / 660, rem = i % 660;
        int yy = rem / 10, xx = rem % 10;
        int y = y0 + yy - 1, xc = xx - 1;
        float v = 0.f;
        if (y >= 0 && y < 256 && xc >= 0 && xc < 8)
            v = x[(((size_t)(b*C + ci)*L + l)*256 + y)*8 + xc];
        xt[i] = v;
    }
    __syncthreads();

    const int yb = tid >> 3, w = tid & 7;
    float acc[2][24];
    #pragma unroll
    for (int r = 0; r < 2; r++)
        #pragma unroll
        for (int o = 0; o < 24; o++) acc[r][o] = 0.f;

    for (int ci = 0; ci < 8; ci++) {
        float xv[2][9];
        #pragma unroll
        for (int r = 0; r < 2; r++)
            #pragma unroll
            for (int ky = 0; ky < 3; ky++)
                #pragma unroll
                for (int kx = 0; kx < 3; kx++)
                    xv[r][ky*3 + kx] = xt[ci*660 + (yb + r*32 + ky)*10 + (w + kx)];
        #pragma unroll
        for (int o = 0; o < 24; o++) {
            int p = o >> 3, co = o & 7;
            const float* wp = &wsm[p*576 + (co*8 + ci)*9];
            #pragma unroll
            for (int k9 = 0; k9 < 9; k9++) {
                float ww = wp[k9];
                acc[0][o] += xv[0][k9] * ww;
                acc[1][o] += xv[1][k9] * ww;
            }
        }
    }
    #pragma unroll
    for (int p = 0; p < 3; p++) {
        hf* oh = (p == 0) ? g_c0 : (p == 1) ? g_c1 : g_c2;
        #pragma unroll
        for (int co = 0; co < 8; co++)
            #pragma unroll
            for (int r = 0; r < 2; r++) {
                size_t off = (size_t)n*16384 + co*2048 + (size_t)(y0 + yb + r*32)*8 + w;
                oh[off] = __float2half_rn(acc[r][p*8 + co]);
            }
    }
}

// ============================================================
// qkv_wm: 3 projections, transposed: outT[g][m] = W[g][:].AT[:][m]
// A = W hi/lo; B = conv single. 3-stage pipeline. RoPE fused.
// grid (64, 2, 24), block 256, 2 CTAs/SM.
// ============================================================
#define QKV_SMEM 87552
__global__ void __launch_bounds__(256, 2)
qkv_wm() {
    extern __shared__ __align__(16) char smem[];
    const uint32_t sb = s2u(smem);
    const int tid = threadIdx.x, wid = tid >> 5;
    const int wm = wid >> 2, wn = wid & 3;
    const int c = blockIdx.z & 7, proj = blockIdx.z >> 3;
    const int m0 = blockIdx.x * 128, g0 = blockIdx.y * 128, n0 = m0 >> 3;
    const hf* Ac  = (proj == 0) ? g_c0 : (proj == 1) ? g_c1 : g_c2;
    const hf* Wh_g = g_wh + (size_t)proj * 524288;
    const hf* Wl_g = g_wl + (size_t)proj * 524288;

    DECL_ACC();

    #define QKVLD(s, kc) { \
        uint32_t sbase = sb + (s) * 29184; int k0 = (kc) * 32; \
        _Pragma("unroll") for (int i = 0; i < 2; i++) { \
            int ch = tid + i * 256; \
            int gr = ch >> 2, c4 = ch & 3; \
            size_t gb = (size_t)c * 65536 + (size_t)(g0 + gr) * 256 + k0 + c4 * 8; \
            cpa16(sbase + gr * 80 + c4 * 16,         Wh_g + gb); \
            cpa16(sbase + 10240 + gr * 80 + c4 * 16, Wl_g + gb); \
            int hr = ch & 31, nl = ch >> 5; \
            size_t ga = (size_t)(n0 + nl) * 16384 + c * 2048 + (size_t)(k0 + hr) * 8; \
            cpa16(sbase + 20480 + hr * 272 + nl * 16, Ac + ga); \
        } }

    QKVLD(0, 0); CPCOMMIT();
    QKVLD(1, 1); CPCOMMIT();
    for (int kc = 0; kc < 8; kc++) {
        if (kc == 7) { CPWAIT(); } else { CPWAIT1(); }
        __syncthreads();
        if (kc < 6) { QKVLD((kc + 2) % 3, kc + 2); CPCOMMIT(); }
        mma2_rArB(smem + (kc % 3) * 29184, wm, wn, acc);
    }

    // Cs holds outT: row = g_rel, col = m_rel = (n-n0)*8 + w
    EPI_TO_CS();
    const float* Cs = (const float*)smem;
    #pragma unroll
    for (int it = 0; it < 8; it++) {
        int p = tid + it * 256;
        int nl = p >> 7, gr = p & 127;      // coalesced stores
        const float* src = Cs + gr * 132 + nl * 8;
        float4 v01 = *(const float4*)(src);
        float4 v23 = *(const float4*)(src + 4);
        float v[8] = {v01.x, v01.y, v01.z, v01.w, v23.x, v23.y, v23.z, v23.w};
        int g = g0 + gr;
        if (proj < 2 && (g & 31) < 4) {        // fused RoPE (q and k)
            int l = (n0 + nl) & 511;
            int jb = (g & 31) * 4;
            #pragma unroll
            for (int t = 0; t < 4; t++) {
                float invf = exp2f(-(float)(jb + t) * (13.287712379549449f / 16.0f));
                float sn, cn;
                sincosf((float)l * invf, &sn, &cn);
                float a = v[2*t], bq = v[2*t+1];
                v[2*t]   = a * cn - bq * sn;
                v[2*t+1] = bq * cn + a * sn;
            }
        }
        size_t e = (size_t)(n0 + nl) * 16384 + (size_t)c * 2048 + (size_t)g * 8;
        if (proj == 0) {
            uint4 H, Lo;
            pack8hl(v, H, Lo);
            *(uint4*)(g_qh + e) = H;
            *(uint4*)(g_ql + e) = Lo;
        } else {
            uint4 H;
            pack8h(v, H);
            *(uint4*)(((proj == 1) ? g_k : g_v) + e) = H;
        }
    }
}

// ============================================================
// qk_wm: 3-stage pipeline. A = Q hi/lo, B = K single.
// Epilogue: qk f32 out + P = exp(qk) hi/lo + atomic row sums.
// grid (4, 4, 128), block 256, 2 CTAs/SM.
// ============================================================
#define QK_SMEM 92160
__global__ void __launch_bounds__(256, 2)
qk_wm(const float* __restrict__ prev, float* __restrict__ qk) {
    extern __shared__ __align__(16) char smem[];
    const uint32_t sb = s2u(smem);
    const int tid = threadIdx.x, wid = tid >> 5;
    const int wm = wid >> 2, wn = wid & 3;
    const int z = blockIdx.z;
    const int b = z >> 6, c = (z >> 3) & 7, nh = z & 7;
    const int l0 = blockIdx.y * 128, m0 = blockIdx.x * 128;
    const size_t coff = (size_t)c * 2048 + nh * 256;
    const size_t bL = (size_t)b * 512;

    DECL_ACC();

    #define QKLD(s, kc) { \
        uint32_t sbase = sb + (s) * 30720; int k0 = (kc) * 32; \
        _Pragma("unroll") for (int i = 0; i < 2; i++) { \
            int ch = tid + i * 256; \
            int r = ch >> 2, c4 = ch & 3; \
            uint32_t so = r * 80 + c4 * 16; \
            size_t ga = (bL + l0 + r) * 16384 + coff + k0 + c4 * 8; \
            size_t gb = (bL + m0 + r) * 16384 + coff + k0 + c4 * 8; \
            cpa16(sbase + so,         g_qh + ga); \
            cpa16(sbase + 10240 + so, g_ql + ga); \
            cpa16(sbase + 20480 + so, g_k + gb); \
        } }

    QKLD(0, 0); CPCOMMIT();
    QKLD(1, 1); CPCOMMIT();
    for (int kc = 0; kc < 8; kc++) {
        if (kc == 7) { CPWAIT(); } else { CPWAIT1(); }
        __syncthreads();
        if (kc < 6) { QKLD((kc + 2) % 3, kc + 2); CPCOMMIT(); }
        mma2_rAcB(smem + (kc % 3) * 30720, wm, wn, acc);
    }

    EPI_TO_CS();
    const float* Cs = (const float*)smem;
    const int col4 = (tid & 31) * 4;
    const int rb = tid >> 5;
    const int lane = tid & 31;
    #pragma unroll 4
    for (int jj = 0; jj < 16; jj++) {
        int r = rb + jj * 8;
        float4 cv = *(const float4*)(Cs + r * 132 + col4);
        size_t idx = (size_t)z * LL + (size_t)(l0 + r) * 512 + m0 + col4;
        float4 pv = *(const float4*)(prev + idx);
        float4 o;
        o.x = cv.x * 0.0625f + pv.x;
        o.y = cv.y * 0.0625f + pv.y;
        o.z = cv.z * 0.0625f + pv.z;
        o.w = cv.w * 0.0625f + pv.w;
        *(float4*)(qk + idx) = o;
        float e0 = __expf(o.x), e1 = __expf(o.y);
        float e2 = __expf(o.z), e3 = __expf(o.w);
        hf h0, lo0, h1, lo1, h2, lo2, h3, lo3;
        hsplit(e0, h0, lo0); hsplit(e1, h1, lo1);
        hsplit(e2, h2, lo2); hsplit(e3, h3, lo3);
        *(uint2*)(g_ph + idx) = make_uint2(packh2(h0, h1), packh2(h2, h3));
        *(uint2*)(g_pl + idx) = make_uint2(packh2(lo0, lo1), packh2(lo2, lo3));
        float s = e0 + e1 + e2 + e3;
        #pragma unroll
        for (int off = 16; off; off >>= 1) s += __shfl_xor_sync(~0u, s, off);
        if (lane == 0) atomicAdd(&g_rsum[z * 512 + l0 + r], s);
    }
}

// ============================================================
// pv_wm: pure 3-stage GEMM. A = P hi/lo, B = V single.
// grid (2, 4, 128), block 256, 2 CTAs/SM. K=512, 16 chunks.
// ============================================================
#define PV_SMEM 88064
__global__ void __launch_bounds__(256, 2)
pv_wm() {
    extern __shared__ __align__(16) char smem[];
    const uint32_t sb = s2u(smem);
    const int tid = threadIdx.x, wid = tid >> 5;
    const int wm = wid >> 2, wn = wid & 3;
    const int z = blockIdx.z;
    const int b = z >> 6, c = (z >> 3) & 7, nh = z & 7;
    const int l0 = blockIdx.y * 128, d0 = blockIdx.x * 128;
    const size_t coff = (size_t)c * 2048 + nh * 256;
    const size_t bL = (size_t)b * 512;
    float* rinv = (float*)(smem + 87552);
    if (tid < 128) rinv[tid] = 1.0f / g_rsum[z * 512 + l0 + tid];

    DECL_ACC();

    #define PVLD(s, kc) { \
        uint32_t sbase = sb + (s) * 29184; int k0 = (kc) * 32; \
        _Pragma("unroll") for (int i = 0; i < 2; i++) { \
            int ch = tid + i * 256; \
            int r = ch >> 2, c4 = ch & 3; \
            size_t gp = (size_t)z * LL + (size_t)(l0 + r) * 512 + k0 + c4 * 8; \
            cpa16(sbase + r * 80 + c4 * 16,         g_ph + gp); \
            cpa16(sbase + 10240 + r * 80 + c4 * 16, g_pl + gp); \
            int mr = ch >> 4, d8 = ch & 15; \
            size_t gv = (bL + k0 + mr) * 16384 + coff + d0 + d8 * 8; \
            cpa16(sbase + 20480 + mr * 272 + d8 * 16, g_v + gv); \
        } }

    PVLD(0, 0); CPCOMMIT();
    PVLD(1, 1); CPCOMMIT();
    for (int kc = 0; kc < 16; kc++) {
        if (kc == 15) { CPWAIT(); } else { CPWAIT1(); }
        __syncthreads();
        if (kc < 14) { PVLD((kc + 2) % 3, kc + 2); CPCOMMIT(); }
        mma2_rArB(smem + (kc % 3) * 29184, wm, wn, acc);
    }

    EPI_TO_CS();
    const float* Cs = (const float*)smem;
    #pragma unroll
    for (int it = 0; it < 8; it++) {
        int r = (tid >> 4) + it * 16;
        int col8 = (tid & 15) * 8;
        float4 a1 = *(const float4*)(Cs + r * 132 + col8);
        float4 a2 = *(const float4*)(Cs + r * 132 + col8 + 4);
        float iv = rinv[r];
        float v[8] = {a1.x*iv, a1.y*iv, a1.z*iv, a1.w*iv, a2.x*iv, a2.y*iv, a2.z*iv, a2.w*iv};
        uint4 H;
        pack8h(v, H);
        size_t e = (bL + l0 + r) * 16384 + coff + d0 + col8;
        *(uint4*)(g_a + e) = H;
    }
}

// ============================================================
// olin_wm: wo projection, transposed: A = wo hi/lo, B = a single.
// 3-stage pipeline. -> f32 out. grid (64, 2, 8), block 256.
// ============================================================
__global__ void __launch_bounds__(256, 2)
olin_wm(float* __restrict__ out) {
    extern __shared__ __align__(16) char smem[];
    const uint32_t sb = s2u(smem);
    const int tid = threadIdx.x, wid = tid >> 5;
    const int wm = wid >> 2, wn = wid & 3;
    const int c = blockIdx.z, m0 = blockIdx.x * 128, g0 = blockIdx.y * 128, n0 = m0 >> 3;
    const hf* Wh_g = g_wh + (size_t)3 * 524288;
    const hf* Wl_g = g_wl + (size_t)3 * 524288;

    DECL_ACC();

    #define OLD(s, kc) { \
        uint32_t sbase = sb + (s) * 29184; int k0 = (kc) * 32; \
        _Pragma("unroll") for (int i = 0; i < 2; i++) { \
            int ch = tid + i * 256; \
            int gr = ch >> 2, c4 = ch & 3; \
            size_t gb = (size_t)c * 65536 + (size_t)(g0 + gr) * 256 + k0 + c4 * 8; \
            cpa16(sbase + gr * 80 + c4 * 16,         Wh_g + gb); \
            cpa16(sbase + 10240 + gr * 80 + c4 * 16, Wl_g + gb); \
            int hr = ch & 31, nl = ch >> 5; \
            size_t ga = (size_t)(n0 + nl) * 16384 + c * 2048 + (size_t)(k0 + hr) * 8; \
            cpa16(sbase + 20480 + hr * 272 + nl * 16, g_a + ga); \
        } }

    OLD(0, 0); CPCOMMIT();
    OLD(1, 1); CPCOMMIT();
    for (int kc = 0; kc < 8; kc++) {
        if (kc == 7) { CPWAIT(); } else { CPWAIT1(); }
        __syncthreads();
        if (kc < 6) { OLD((kc + 2) % 3, kc + 2); CPCOMMIT(); }
        mma2_rArB(smem + (kc % 3) * 29184, wm, wn, acc);
    }

    EPI_TO_CS();
    const float* Cs = (const float*)smem;
    #pragma unroll
    for (int it = 0; it < 8; it++) {
        int p = tid + it * 256;
        int nl = p >> 7, gr = p & 127;      // coalesced stores
        int n = n0 + nl, bb = n >> 9, l = n & 511;
        float4 o1 = *(const float4*)(Cs + gr * 132 + nl * 8);
        float4 o2 = *(const float4*)(Cs + gr * 132 + nl * 8 + 4);
        size_t e = ((size_t)(bb * 8 + c) * 512 + l) * 2048 + (size_t)(g0 + gr) * 8;
        *(float4*)(out + e)     = o1;
        *(float4*)(out + e + 4) = o2;
    }
}

// ============================================================
extern "C" void kernel_launch(void* const* d_in, const int* in_sizes, int n_in,
                              void* d_out, int out_size) {
    const float* x    = (const float*)d_in[0];
    const float* prev = (const float*)d_in[1];
    const float* cw_q = (const float*)d_in[2];
    const float* cw_k = (const float*)d_in[3];
    const float* cw_v = (const float*)d_in[4];
    const float* wq   = (const float*)d_in[5];
    const float* wk   = (const float*)d_in[6];
    const float* wv   = (const float*)d_in[7];
    const float* wo   = (const float*)d_in[8];
    float* out    = (float*)d_out;
    float* qk_out = out + (size_t)NCF;

    cudaFuncSetAttribute(qkv_wm,  cudaFuncAttributeMaxDynamicSharedMemorySize, QKV_SMEM);
    cudaFuncSetAttribute(olin_wm, cudaFuncAttributeMaxDynamicSharedMemorySize, QKV_SMEM);
    cudaFuncSetAttribute(qk_wm,   cudaFuncAttributeMaxDynamicSharedMemorySize, QK_SMEM);
    cudaFuncSetAttribute(pv_wm,   cudaFuncAttributeMaxDynamicSharedMemorySize, PV_SMEM);

    conv3_kernel<<<dim3(3072, 4), 256>>>(x, cw_q, cw_k, cw_v, wq, wk, wv, wo);
    qkv_wm<<<dim3(64, 2, 24), 256, QKV_SMEM>>>();
    qk_wm<<<dim3(4, 4, 128), 256, QK_SMEM>>>(prev, qk_out);
    pv_wm<<<dim3(2, 4, 128), 256, PV_SMEM>>>();
    olin_wm<<<dim3(64, 2, 8), 256, QKV_SMEM>>>(out);
}

// round 15
// speedup vs baseline: 1.4345x; 1.0090x over previous
#include <cuda_runtime.h>
#include <cuda_fp16.h>
#include <mma.h>
#include <math.h>
#include <cstdint>

using namespace nvcuda;
typedef __half hf;

#define C    8
#define L    512
#define NCF  (1024*8*2048)     // 16,777,216
#define LL   (512*512)

// ---- fp16 scratch: A-side tensors hi+lo, B-side hi only ----
__device__ hf g_c0[NCF], g_c1[NCF], g_c2[NCF];       // conv outs (B-side)
__device__ hf g_qh[NCF], g_ql[NCF];                  // q (A-side in qk)
__device__ hf g_k[NCF];                              // k (B-side)
__device__ hf g_v[NCF];                              // v (B-side)
__device__ hf g_a[NCF];                              // attn out (B-side in olin)
__device__ hf g_ph[128*LL], g_pl[128*LL];            // P (A-side in pv)
__device__ hf g_wh[4*C*65536], g_wl[4*C*65536];      // weights (A-side)
__device__ float g_rsum[65536];

// ---- helpers ----
__device__ __forceinline__ uint32_t s2u(const void* p) {
    return (uint32_t)__cvta_generic_to_shared(p);
}
__device__ __forceinline__ void cpa16(uint32_t s, const void* g) {
    asm volatile("cp.async.cg.shared.global [%0], [%1], 16;" :: "r"(s), "l"(g));
}
#define CPCOMMIT() asm volatile("cp.async.commit_group;" ::: "memory")
#define CPWAIT()   asm volatile("cp.async.wait_group 0;" ::: "memory")
#define CPWAIT1()  asm volatile("cp.async.wait_group 1;" ::: "memory")

__device__ __forceinline__ void hsplit(float x, hf& h, hf& l) {
    h = __float2half_rn(x);
    l = __float2half_rn(x - __half2float(h));
}
__device__ __forceinline__ uint32_t packh2(hf a, hf b) {
    __half2 t = __halves2half2(a, b);
    return *(uint32_t*)&t;
}
__device__ __forceinline__ void pack8hl(const float* v, uint4& H, uint4& Lo) {
    hf h[8], l[8];
    #pragma unroll
    for (int i = 0; i < 8; i++) hsplit(v[i], h[i], l[i]);
    H  = make_uint4(packh2(h[0],h[1]), packh2(h[2],h[3]), packh2(h[4],h[5]), packh2(h[6],h[7]));
    Lo = make_uint4(packh2(l[0],l[1]), packh2(l[2],l[3]), packh2(l[4],l[5]), packh2(l[6],l[7]));
}
__device__ __forceinline__ void pack8h(const float* v, uint4& H) {
    hf h[8];
    #pragma unroll
    for (int i = 0; i < 8; i++) h[i] = __float2half_rn(v[i]);
    H = make_uint4(packh2(h[0],h[1]), packh2(h[2],h[3]), packh2(h[4],h[5]), packh2(h[6],h[7]));
}

typedef wmma::fragment<wmma::accumulator, 16, 16, 16, float> AccFrag;

// Warp grid: 4x2 (wm in 0..3 over 32-row tiles, wn in 0..1 over 64-col tiles).
// Per-warp tile 32x64, acc[2][4]. Fragment loads per chunk: A 8 + B 8 = 16
// (vs 20 for 2x4) -> -20% mainloop smem traffic.

// stage layouts (bytes), per stage:
//  qk  (30720): Qh 0  Ql 10240  K 20480       [K-major 128x40 hf, ldm 40]
//  qkv (29184): Wh 0  Wl 10240  AT 20480      [AT: 32x136 hf, ldm 136]
//  pv  (29184): Ph 0  Pl 10240  V 20480       [V: 32x136 hf, ldm 136]

// A (hi/lo) row_major K-major ldm 40; B single col_major K-major ldm 40
__device__ __forceinline__ void mma2_rAcB(const char* buf, int wm, int wn, AccFrag (&acc)[2][4]) {
    const hf* Ah = (const hf*)(buf);
    const hf* Al = (const hf*)(buf + 10240);
    const hf* B  = (const hf*)(buf + 20480);
    #pragma unroll
    for (int ks = 0; ks < 2; ks++) {
        wmma::fragment<wmma::matrix_b, 16, 16, 16, hf, wmma::col_major> bf[4];
        #pragma unroll
        for (int j = 0; j < 4; j++)
            wmma::load_matrix_sync(bf[j], B + (wn * 64 + j * 16) * 40 + ks * 16, 40);
        #pragma unroll
        for (int i = 0; i < 2; i++) {
            int m_off = wm * 32 + i * 16;
            wmma::fragment<wmma::matrix_a, 16, 16, 16, hf, wmma::row_major> ah, al;
            wmma::load_matrix_sync(ah, Ah + m_off * 40 + ks * 16, 40);
            wmma::load_matrix_sync(al, Al + m_off * 40 + ks * 16, 40);
            #pragma unroll
            for (int j = 0; j < 4; j++) {
                wmma::mma_sync(acc[i][j], ah, bf[j], acc[i][j]);
                wmma::mma_sync(acc[i][j], al, bf[j], acc[i][j]);
            }
        }
    }
}

// A (hi/lo) row_major K-major ldm 40; B single row_major [k][n] ldm 136
__device__ __forceinline__ void mma2_rArB(const char* buf, int wm, int wn, AccFrag (&acc)[2][4]) {
    const hf* Ah = (const hf*)(buf);
    const hf* Al = (const hf*)(buf + 10240);
    const hf* B  = (const hf*)(buf + 20480);
    #pragma unroll
    for (int ks = 0; ks < 2; ks++) {
        wmma::fragment<wmma::matrix_b, 16, 16, 16, hf, wmma::row_major> bf[4];
        #pragma unroll
        for (int j = 0; j < 4; j++)
            wmma::load_matrix_sync(bf[j], B + (ks * 16) * 136 + wn * 64 + j * 16, 136);
        #pragma unroll
        for (int i = 0; i < 2; i++) {
            int m_off = wm * 32 + i * 16;
            wmma::fragment<wmma::matrix_a, 16, 16, 16, hf, wmma::row_major> ah, al;
            wmma::load_matrix_sync(ah, Ah + m_off * 40 + ks * 16, 40);
            wmma::load_matrix_sync(al, Al + m_off * 40 + ks * 16, 40);
            #pragma unroll
            for (int j = 0; j < 4; j++) {
                wmma::mma_sync(acc[i][j], ah, bf[j], acc[i][j]);
                wmma::mma_sync(acc[i][j], al, bf[j], acc[i][j]);
            }
        }
    }
}

#define DECL_ACC() \
    AccFrag acc[2][4]; \
    _Pragma("unroll") for (int i_ = 0; i_ < 2; i_++) \
        _Pragma("unroll") for (int j_ = 0; j_ < 4; j_++) wmma::fill_fragment(acc[i_][j_], 0.0f);

#define EPI_TO_CS() \
    __syncthreads(); \
    { float* Cs_ = (float*)smem; \
      _Pragma("unroll") for (int i_ = 0; i_ < 2; i_++) \
        _Pragma("unroll") for (int j_ = 0; j_ < 4; j_++) \
          wmma::store_matrix_sync(Cs_ + (wm*32 + i_*16)*132 + wn*64 + j_*16, acc[i_][j_], 132, wmma::mem_row_major); } \
    __syncthreads();

// ============================================================
// conv3 + prep_w fused launch.
// blockIdx.x < 1024: conv; >= 1024: weight-split + rsum zero.
// ============================================================
__global__ void conv3_kernel(const float* __restrict__ x,
                             const float* __restrict__ wq,
                             const float* __restrict__ wk,
                             const float* __restrict__ wv,
                             const float* __restrict__ lwq, const float* __restrict__ lwk,
                             const float* __restrict__ lwv, const float* __restrict__ lwo) {
    __shared__ float xt[8*66*10];
    __shared__ float wsm[3*576];
    const int tid = threadIdx.x;

    if (blockIdx.x >= 1024) {
        int idx = (((blockIdx.x - 1024) * 4 + blockIdx.y)) * 256 + tid;   // 0 .. 2M-1
        if (idx < 65536) g_rsum[idx] = 0.0f;
        int t = idx >> 19, off = idx & 524287;
        const float* src = (t == 0) ? lwq : (t == 1) ? lwk : (t == 2) ? lwv : lwo;
        hf h, l;
        hsplit(src[off], h, l);
        g_wh[idx] = h; g_wl[idx] = l;
        return;
    }

    const int n  = blockIdx.x;
    const int y0 = blockIdx.y * 64;
    const int b  = n >> 9, l = n & 511;

    for (int i = tid; i < 576; i += 256) {
        wsm[i] = wq[i]; wsm[576 + i] = wk[i]; wsm[1152 + i] = wv[i];
    }
    for (int i = tid; i < 8*66*10; i += 256) {
        int ci = i / 660, rem = i % 660;
        int yy = rem / 10, xx = rem % 10;
        int y = y0 + yy - 1, xc = xx - 1;
        float v = 0.f;
        if (y >= 0 && y < 256 && xc >= 0 && xc < 8)
            v = x[(((size_t)(b*C + ci)*L + l)*256 + y)*8 + xc];
        xt[i] = v;
    }
    __syncthreads();

    const int yb = tid >> 3, w = tid & 7;
    float acc[2][24];
    #pragma unroll
    for (int r = 0; r < 2; r++)
        #pragma unroll
        for (int o = 0; o < 24; o++) acc[r][o] = 0.f;

    for (int ci = 0; ci < 8; ci++) {
        float xv[2][9];
        #pragma unroll
        for (int r = 0; r < 2; r++)
            #pragma unroll
            for (int ky = 0; ky < 3; ky++)
                #pragma unroll
                for (int kx = 0; kx < 3; kx++)
                    xv[r][ky*3 + kx] = xt[ci*660 + (yb + r*32 + ky)*10 + (w + kx)];
        #pragma unroll
        for (int o = 0; o < 24; o++) {
            int p = o >> 3, co = o & 7;
            const float* wp = &wsm[p*576 + (co*8 + ci)*9];
            #pragma unroll
            for (int k9 = 0; k9 < 9; k9++) {
                float ww = wp[k9];
                acc[0][o] += xv[0][k9] * ww;
                acc[1][o] += xv[1][k9] * ww;
            }
        }
    }
    #pragma unroll
    for (int p = 0; p < 3; p++) {
        hf* oh = (p == 0) ? g_c0 : (p == 1) ? g_c1 : g_c2;
        #pragma unroll
        for (int co = 0; co < 8; co++)
            #pragma unroll
            for (int r = 0; r < 2; r++) {
                size_t off = (size_t)n*16384 + co*2048 + (size_t)(y0 + yb + r*32)*8 + w;
                oh[off] = __float2half_rn(acc[r][p*8 + co]);
            }
    }
}

// ============================================================
// qkv_wm: 3 projections, transposed: outT[g][m] = W[g][:].AT[:][m]
// A = W hi/lo; B = conv single. 3-stage pipeline. RoPE fused.
// grid (64, 2, 24), block 256, 2 CTAs/SM.
// ============================================================
#define QKV_SMEM 87552
__global__ void __launch_bounds__(256, 2)
qkv_wm() {
    extern __shared__ __align__(16) char smem[];
    const uint32_t sb = s2u(smem);
    const int tid = threadIdx.x, wid = tid >> 5;
    const int wm = wid >> 1, wn = wid & 1;
    const int c = blockIdx.z & 7, proj = blockIdx.z >> 3;
    const int m0 = blockIdx.x * 128, g0 = blockIdx.y * 128, n0 = m0 >> 3;
    const hf* Ac  = (proj == 0) ? g_c0 : (proj == 1) ? g_c1 : g_c2;
    const hf* Wh_g = g_wh + (size_t)proj * 524288;
    const hf* Wl_g = g_wl + (size_t)proj * 524288;

    DECL_ACC();

    #define QKVLD(s, kc) { \
        uint32_t sbase = sb + (s) * 29184; int k0 = (kc) * 32; \
        _Pragma("unroll") for (int i = 0; i < 2; i++) { \
            int ch = tid + i * 256; \
            int gr = ch >> 2, c4 = ch & 3; \
            size_t gb = (size_t)c * 65536 + (size_t)(g0 + gr) * 256 + k0 + c4 * 8; \
            cpa16(sbase + gr * 80 + c4 * 16,         Wh_g + gb); \
            cpa16(sbase + 10240 + gr * 80 + c4 * 16, Wl_g + gb); \
            int hr = ch & 31, nl = ch >> 5; \
            size_t ga = (size_t)(n0 + nl) * 16384 + c * 2048 + (size_t)(k0 + hr) * 8; \
            cpa16(sbase + 20480 + hr * 272 + nl * 16, Ac + ga); \
        } }

    QKVLD(0, 0); CPCOMMIT();
    QKVLD(1, 1); CPCOMMIT();
    for (int kc = 0; kc < 8; kc++) {
        if (kc == 7) { CPWAIT(); } else { CPWAIT1(); }
        __syncthreads();
        if (kc < 6) { QKVLD((kc + 2) % 3, kc + 2); CPCOMMIT(); }
        mma2_rArB(smem + (kc % 3) * 29184, wm, wn, acc);
    }

    // Cs holds outT: row = g_rel, col = m_rel = (n-n0)*8 + w
    EPI_TO_CS();
    const float* Cs = (const float*)smem;
    #pragma unroll
    for (int it = 0; it < 8; it++) {
        int p = tid + it * 256;
        int nl = p >> 7, gr = p & 127;      // coalesced stores
        const float* src = Cs + gr * 132 + nl * 8;
        float4 v01 = *(const float4*)(src);
        float4 v23 = *(const float4*)(src + 4);
        float v[8] = {v01.x, v01.y, v01.z, v01.w, v23.x, v23.y, v23.z, v23.w};
        int g = g0 + gr;
        if (proj < 2 && (g & 31) < 4) {        // fused RoPE (q and k)
            int l = (n0 + nl) & 511;
            int jb = (g & 31) * 4;
            #pragma unroll
            for (int t = 0; t < 4; t++) {
                float invf = exp2f(-(float)(jb + t) * (13.287712379549449f / 16.0f));
                float sn, cn;
                sincosf((float)l * invf, &sn, &cn);
                float a = v[2*t], bq = v[2*t+1];
                v[2*t]   = a * cn - bq * sn;
                v[2*t+1] = bq * cn + a * sn;
            }
        }
        size_t e = (size_t)(n0 + nl) * 16384 + (size_t)c * 2048 + (size_t)g * 8;
        if (proj == 0) {
            uint4 H, Lo;
            pack8hl(v, H, Lo);
            *(uint4*)(g_qh + e) = H;
            *(uint4*)(g_ql + e) = Lo;
        } else {
            uint4 H;
            pack8h(v, H);
            *(uint4*)(((proj == 1) ? g_k : g_v) + e) = H;
        }
    }
}

// ============================================================
// qk_wm: 3-stage pipeline. A = Q hi/lo, B = K single.
// Epilogue: qk f32 out + P = exp(qk) hi/lo + atomic row sums.
// grid (4, 4, 128), block 256, 2 CTAs/SM.
// ============================================================
#define QK_SMEM 92160
__global__ void __launch_bounds__(256, 2)
qk_wm(const float* __restrict__ prev, float* __restrict__ qk) {
    extern __shared__ __align__(16) char smem[];
    const uint32_t sb = s2u(smem);
    const int tid = threadIdx.x, wid = tid >> 5;
    const int wm = wid >> 1, wn = wid & 1;
    const int z = blockIdx.z;
    const int b = z >> 6, c = (z >> 3) & 7, nh = z & 7;
    const int l0 = blockIdx.y * 128, m0 = blockIdx.x * 128;
    const size_t coff = (size_t)c * 2048 + nh * 256;
    const size_t bL = (size_t)b * 512;

    DECL_ACC();

    #define QKLD(s, kc) { \
        uint32_t sbase = sb + (s) * 30720; int k0 = (kc) * 32; \
        _Pragma("unroll") for (int i = 0; i < 2; i++) { \
            int ch = tid + i * 256; \
            int r = ch >> 2, c4 = ch & 3; \
            uint32_t so = r * 80 + c4 * 16; \
            size_t ga = (bL + l0 + r) * 16384 + coff + k0 + c4 * 8; \
            size_t gb = (bL + m0 + r) * 16384 + coff + k0 + c4 * 8; \
            cpa16(sbase + so,         g_qh + ga); \
            cpa16(sbase + 10240 + so, g_ql + ga); \
            cpa16(sbase + 20480 + so, g_k + gb); \
        } }

    QKLD(0, 0); CPCOMMIT();
    QKLD(1, 1); CPCOMMIT();
    for (int kc = 0; kc < 8; kc++) {
        if (kc == 7) { CPWAIT(); } else { CPWAIT1(); }
        __syncthreads();
        if (kc < 6) { QKLD((kc + 2) % 3, kc + 2); CPCOMMIT(); }
        mma2_rAcB(smem + (kc % 3) * 30720, wm, wn, acc);
    }

    EPI_TO_CS();
    const float* Cs = (const float*)smem;
    const int col4 = (tid & 31) * 4;
    const int rb = tid >> 5;
    const int lane = tid & 31;
    #pragma unroll 4
    for (int jj = 0; jj < 16; jj++) {
        int r = rb + jj * 8;
        float4 cv = *(const float4*)(Cs + r * 132 + col4);
        size_t idx = (size_t)z * LL + (size_t)(l0 + r) * 512 + m0 + col4;
        float4 pv = *(const float4*)(prev + idx);
        float4 o;
        o.x = cv.x * 0.0625f + pv.x;
        o.y = cv.y * 0.0625f + pv.y;
        o.z = cv.z * 0.0625f + pv.z;
        o.w = cv.w * 0.0625f + pv.w;
        *(float4*)(qk + idx) = o;
        float e0 = __expf(o.x), e1 = __expf(o.y);
        float e2 = __expf(o.z), e3 = __expf(o.w);
        hf h0, lo0, h1, lo1, h2, lo2, h3, lo3;
        hsplit(e0, h0, lo0); hsplit(e1, h1, lo1);
        hsplit(e2, h2, lo2); hsplit(e3, h3, lo3);
        *(uint2*)(g_ph + idx) = make_uint2(packh2(h0, h1), packh2(h2, h3));
        *(uint2*)(g_pl + idx) = make_uint2(packh2(lo0, lo1), packh2(lo2, lo3));
        float s = e0 + e1 + e2 + e3;
        #pragma unroll
        for (int off = 16; off; off >>= 1) s += __shfl_xor_sync(~0u, s, off);
        if (lane == 0) atomicAdd(&g_rsum[z * 512 + l0 + r], s);
    }
}

// ============================================================
// pv_wm: pure 3-stage GEMM. A = P hi/lo, B = V single.
// grid (2, 4, 128), block 256, 2 CTAs/SM. K=512, 16 chunks.
// ============================================================
#define PV_SMEM 88064
__global__ void __launch_bounds__(256, 2)
pv_wm() {
    extern __shared__ __align__(16) char smem[];
    const uint32_t sb = s2u(smem);
    const int tid = threadIdx.x, wid = tid >> 5;
    const int wm = wid >> 1, wn = wid & 1;
    const int z = blockIdx.z;
    const int b = z >> 6, c = (z >> 3) & 7, nh = z & 7;
    const int l0 = blockIdx.y * 128, d0 = blockIdx.x * 128;
    const size_t coff = (size_t)c * 2048 + nh * 256;
    const size_t bL = (size_t)b * 512;
    float* rinv = (float*)(smem + 87552);
    if (tid < 128) rinv[tid] = 1.0f / g_rsum[z * 512 + l0 + tid];

    DECL_ACC();

    #define PVLD(s, kc) { \
        uint32_t sbase = sb + (s) * 29184; int k0 = (kc) * 32; \
        _Pragma("unroll") for (int i = 0; i < 2; i++) { \
            int ch = tid + i * 256; \
            int r = ch >> 2, c4 = ch & 3; \
            size_t gp = (size_t)z * LL + (size_t)(l0 + r) * 512 + k0 + c4 * 8; \
            cpa16(sbase + r * 80 + c4 * 16,         g_ph + gp); \
            cpa16(sbase + 10240 + r * 80 + c4 * 16, g_pl + gp); \
            int mr = ch >> 4, d8 = ch & 15; \
            size_t gv = (bL + k0 + mr) * 16384 + coff + d0 + d8 * 8; \
            cpa16(sbase + 20480 + mr * 272 + d8 * 16, g_v + gv); \
        } }

    PVLD(0, 0); CPCOMMIT();
    PVLD(1, 1); CPCOMMIT();
    for (int kc = 0; kc < 16; kc++) {
        if (kc == 15) { CPWAIT(); } else { CPWAIT1(); }
        __syncthreads();
        if (kc < 14) { PVLD((kc + 2) % 3, kc + 2); CPCOMMIT(); }
        mma2_rArB(smem + (kc % 3) * 29184, wm, wn, acc);
    }

    EPI_TO_CS();
    const float* Cs = (const float*)smem;
    #pragma unroll
    for (int it = 0; it < 8; it++) {
        int r = (tid >> 4) + it * 16;
        int col8 = (tid & 15) * 8;
        float4 a1 = *(const float4*)(Cs + r * 132 + col8);
        float4 a2 = *(const float4*)(Cs + r * 132 + col8 + 4);
        float iv = rinv[r];
        float v[8] = {a1.x*iv, a1.y*iv, a1.z*iv, a1.w*iv, a2.x*iv, a2.y*iv, a2.z*iv, a2.w*iv};
        uint4 H;
        pack8h(v, H);
        size_t e = (bL + l0 + r) * 16384 + coff + d0 + col8;
        *(uint4*)(g_a + e) = H;
    }
}

// ============================================================
// olin_wm: wo projection, transposed: A = wo hi/lo, B = a single.
// 3-stage pipeline. -> f32 out. grid (64, 2, 8), block 256.
// ============================================================
__global__ void __launch_bounds__(256, 2)
olin_wm(float* __restrict__ out) {
    extern __shared__ __align__(16) char smem[];
    const uint32_t sb = s2u(smem);
    const int tid = threadIdx.x, wid = tid >> 5;
    const int wm = wid >> 1, wn = wid & 1;
    const int c = blockIdx.z, m0 = blockIdx.x * 128, g0 = blockIdx.y * 128, n0 = m0 >> 3;
    const hf* Wh_g = g_wh + (size_t)3 * 524288;
    const hf* Wl_g = g_wl + (size_t)3 * 524288;

    DECL_ACC();

    #define OLD(s, kc) { \
        uint32_t sbase = sb + (s) * 29184; int k0 = (kc) * 32; \
        _Pragma("unroll") for (int i = 0; i < 2; i++) { \
            int ch = tid + i * 256; \
            int gr = ch >> 2, c4 = ch & 3; \
            size_t gb = (size_t)c * 65536 + (size_t)(g0 + gr) * 256 + k0 + c4 * 8; \
            cpa16(sbase + gr * 80 + c4 * 16,         Wh_g + gb); \
            cpa16(sbase + 10240 + gr * 80 + c4 * 16, Wl_g + gb); \
            int hr = ch & 31, nl = ch >> 5; \
            size_t ga = (size_t)(n0 + nl) * 16384 + c * 2048 + (size_t)(k0 + hr) * 8; \
            cpa16(sbase + 20480 + hr * 272 + nl * 16, g_a + ga); \
        } }

    OLD(0, 0); CPCOMMIT();
    OLD(1, 1); CPCOMMIT();
    for (int kc = 0; kc < 8; kc++) {
        if (kc == 7) { CPWAIT(); } else { CPWAIT1(); }
        __syncthreads();
        if (kc < 6) { OLD((kc + 2) % 3, kc + 2); CPCOMMIT(); }
        mma2_rArB(smem + (kc % 3) * 29184, wm, wn, acc);
    }

    EPI_TO_CS();
    const float* Cs = (const float*)smem;
    #pragma unroll
    for (int it = 0; it < 8; it++) {
        int p = tid + it * 256;
        int nl = p >> 7, gr = p & 127;      // coalesced stores
        int n = n0 + nl, bb = n >> 9, l = n & 511;
        float4 o1 = *(const float4*)(Cs + gr * 132 + nl * 8);
        float4 o2 = *(const float4*)(Cs + gr * 132 + nl * 8 + 4);
        size_t e = ((size_t)(bb * 8 + c) * 512 + l) * 2048 + (size_t)(g0 + gr) * 8;
        *(float4*)(out + e)     = o1;
        *(float4*)(out + e + 4) = o2;
    }
}

// ============================================================
extern "C" void kernel_launch(void* const* d_in, const int* in_sizes, int n_in,
                              void* d_out, int out_size) {
    const float* x    = (const float*)d_in[0];
    const float* prev = (const float*)d_in[1];
    const float* cw_q = (const float*)d_in[2];
    const float* cw_k = (const float*)d_in[3];
    const float* cw_v = (const float*)d_in[4];
    const float* wq   = (const float*)d_in[5];
    const float* wk   = (const float*)d_in[6];
    const float* wv   = (const float*)d_in[7];
    const float* wo   = (const float*)d_in[8];
    float* out    = (float*)d_out;
    float* qk_out = out + (size_t)NCF;

    cudaFuncSetAttribute(qkv_wm,  cudaFuncAttributeMaxDynamicSharedMemorySize, QKV_SMEM);
    cudaFuncSetAttribute(olin_wm, cudaFuncAttributeMaxDynamicSharedMemorySize, QKV_SMEM);
    cudaFuncSetAttribute(qk_wm,   cudaFuncAttributeMaxDynamicSharedMemorySize, QK_SMEM);
    cudaFuncSetAttribute(pv_wm,   cudaFuncAttributeMaxDynamicSharedMemorySize, PV_SMEM);

    conv3_kernel<<<dim3(3072, 4), 256>>>(x, cw_q, cw_k, cw_v, wq, wk, wv, wo);
    qkv_wm<<<dim3(64, 2, 24), 256, QKV_SMEM>>>();
    qk_wm<<<dim3(4, 4, 128), 256, QK_SMEM>>>(prev, qk_out);
    pv_wm<<<dim3(2, 4, 128), 256, PV_SMEM>>>();
    olin_wm<<<dim3(64, 2, 8), 256, QKV_SMEM>>>(out);
}

// round 16
// speedup vs baseline: 1.4734x; 1.0271x over previous
#include <cuda_runtime.h>
#include <cuda_fp16.h>
#include <mma.h>
#include <math.h>
#include <cstdint>

using namespace nvcuda;
typedef __half hf;

#define C    8
#define L    512
#define NCF  (1024*8*2048)     // 16,777,216
#define LL   (512*512)

// ---- fp16 scratch: A-side tensors hi+lo, B-side hi only ----
__device__ hf g_c0[NCF], g_c1[NCF], g_c2[NCF];       // conv outs (B-side)
__device__ hf g_qh[NCF], g_ql[NCF];                  // q (A-side in qk)
__device__ hf g_k[NCF];                              // k (B-side)
__device__ hf g_v[NCF];                              // v (B-side)
__device__ hf g_a[NCF];                              // attn out (B-side in olin)
__device__ hf g_ph[128*LL], g_pl[128*LL];            // P hi/lo (A-side in pv)
__device__ hf g_wh[4*C*65536], g_wl[4*C*65536];      // weights (A-side)
__device__ float g_rsum[65536];

// ---- helpers ----
__device__ __forceinline__ uint32_t s2u(const void* p) {
    return (uint32_t)__cvta_generic_to_shared(p);
}
__device__ __forceinline__ void cpa16(uint32_t s, const void* g) {
    asm volatile("cp.async.cg.shared.global [%0], [%1], 16;" :: "r"(s), "l"(g));
}
#define CPCOMMIT() asm volatile("cp.async.commit_group;" ::: "memory")
#define CPWAIT()   asm volatile("cp.async.wait_group 0;" ::: "memory")

__device__ __forceinline__ void hsplit(float x, hf& h, hf& l) {
    h = __float2half_rn(x);
    l = __float2half_rn(x - __half2float(h));
}
__device__ __forceinline__ uint32_t packh2(hf a, hf b) {
    __half2 t = __halves2half2(a, b);
    return *(uint32_t*)&t;
}
__device__ __forceinline__ void pack8hl(const float* v, uint4& H, uint4& Lo) {
    hf h[8], l[8];
    #pragma unroll
    for (int i = 0; i < 8; i++) hsplit(v[i], h[i], l[i]);
    H  = make_uint4(packh2(h[0],h[1]), packh2(h[2],h[3]), packh2(h[4],h[5]), packh2(h[6],h[7]));
    Lo = make_uint4(packh2(l[0],l[1]), packh2(l[2],l[3]), packh2(l[4],l[5]), packh2(l[6],l[7]));
}
__device__ __forceinline__ void pack8h(const float* v, uint4& H) {
    hf h[8];
    #pragma unroll
    for (int i = 0; i < 8; i++) h[i] = __float2half_rn(v[i]);
    H = make_uint4(packh2(h[0],h[1]), packh2(h[2],h[3]), packh2(h[4],h[5]), packh2(h[6],h[7]));
}

typedef wmma::fragment<wmma::accumulator, 16, 16, 16, float> AccFrag;

// Warp grid 4x2 (wm: 32-row tiles, wn: 64-col tiles), acc[2][4].
// K-chunk = 64 (4 ks steps), 2 smem stages -> half the barriers.
// stage layouts (bytes):
//  qk  (55296): Qh 0  Ql 18432  K 36864     [K-major 128x72 hf, ldm 72]
//  qkv (54272): Wh 0  Wl 18432  AT 36864    [A 128x72 ldm 72; AT 64x136 ldm 136]
//  pv  (54272): Ph 0  Pl 18432  V 36864     [V 64x136 ldm 136]

// A (hi/lo) row_major K-major ldm 72; B single col_major K-major ldm 72
__device__ __forceinline__ void mma2_rAcB(const char* buf, int wm, int wn, AccFrag (&acc)[2][4]) {
    const hf* Ah = (const hf*)(buf);
    const hf* Al = (const hf*)(buf + 18432);
    const hf* B  = (const hf*)(buf + 36864);
    #pragma unroll
    for (int ks = 0; ks < 4; ks++) {
        wmma::fragment<wmma::matrix_b, 16, 16, 16, hf, wmma::col_major> bf[4];
        #pragma unroll
        for (int j = 0; j < 4; j++)
            wmma::load_matrix_sync(bf[j], B + (wn * 64 + j * 16) * 72 + ks * 16, 72);
        #pragma unroll
        for (int i = 0; i < 2; i++) {
            int m_off = wm * 32 + i * 16;
            wmma::fragment<wmma::matrix_a, 16, 16, 16, hf, wmma::row_major> ah, al;
            wmma::load_matrix_sync(ah, Ah + m_off * 72 + ks * 16, 72);
            wmma::load_matrix_sync(al, Al + m_off * 72 + ks * 16, 72);
            #pragma unroll
            for (int j = 0; j < 4; j++) {
                wmma::mma_sync(acc[i][j], ah, bf[j], acc[i][j]);
                wmma::mma_sync(acc[i][j], al, bf[j], acc[i][j]);
            }
        }
    }
}

// A (hi/lo) row_major K-major ldm 72; B single row_major [k][n] ldm 136
__device__ __forceinline__ void mma2_rArB(const char* buf, int wm, int wn, AccFrag (&acc)[2][4]) {
    const hf* Ah = (const hf*)(buf);
    const hf* Al = (const hf*)(buf + 18432);
    const hf* B  = (const hf*)(buf + 36864);
    #pragma unroll
    for (int ks = 0; ks < 4; ks++) {
        wmma::fragment<wmma::matrix_b, 16, 16, 16, hf, wmma::row_major> bf[4];
        #pragma unroll
        for (int j = 0; j < 4; j++)
            wmma::load_matrix_sync(bf[j], B + (ks * 16) * 136 + wn * 64 + j * 16, 136);
        #pragma unroll
        for (int i = 0; i < 2; i++) {
            int m_off = wm * 32 + i * 16;
            wmma::fragment<wmma::matrix_a, 16, 16, 16, hf, wmma::row_major> ah, al;
            wmma::load_matrix_sync(ah, Ah + m_off * 72 + ks * 16, 72);
            wmma::load_matrix_sync(al, Al + m_off * 72 + ks * 16, 72);
            #pragma unroll
            for (int j = 0; j < 4; j++) {
                wmma::mma_sync(acc[i][j], ah, bf[j], acc[i][j]);
                wmma::mma_sync(acc[i][j], al, bf[j], acc[i][j]);
            }
        }
    }
}

#define DECL_ACC() \
    AccFrag acc[2][4]; \
    _Pragma("unroll") for (int i_ = 0; i_ < 2; i_++) \
        _Pragma("unroll") for (int j_ = 0; j_ < 4; j_++) wmma::fill_fragment(acc[i_][j_], 0.0f);

#define EPI_TO_CS() \
    __syncthreads(); \
    { float* Cs_ = (float*)smem; \
      _Pragma("unroll") for (int i_ = 0; i_ < 2; i_++) \
        _Pragma("unroll") for (int j_ = 0; j_ < 4; j_++) \
          wmma::store_matrix_sync(Cs_ + (wm*32 + i_*16)*132 + wn*64 + j_*16, acc[i_][j_], 132, wmma::mem_row_major); } \
    __syncthreads();

// ============================================================
// conv3 + prep_w fused launch.
// ============================================================
__global__ void conv3_kernel(const float* __restrict__ x,
                             const float* __restrict__ wq,
                             const float* __restrict__ wk,
                             const float* __restrict__ wv,
                             const float* __restrict__ lwq, const float* __restrict__ lwk,
                             const float* __restrict__ lwv, const float* __restrict__ lwo) {
    __shared__ float xt[8*66*10];
    __shared__ float wsm[3*576];
    const int tid = threadIdx.x;

    if (blockIdx.x >= 1024) {
        int idx = (((blockIdx.x - 1024) * 4 + blockIdx.y)) * 256 + tid;
        if (idx < 65536) g_rsum[idx] = 0.0f;
        int t = idx >> 19, off = idx & 524287;
        const float* src = (t == 0) ? lwq : (t == 1) ? lwk : (t == 2) ? lwv : lwo;
        hf h, l;
        hsplit(src[off], h, l);
        g_wh[idx] = h; g_wl[idx] = l;
        return;
    }

    const int n  = blockIdx.x;
    const int y0 = blockIdx.y * 64;
    const int b  = n >> 9, l = n & 511;

    for (int i = tid; i < 576; i += 256) {
        wsm[i] = wq[i]; wsm[576 + i] = wk[i]; wsm[1152 + i] = wv[i];
    }
    for (int i = tid; i < 8*66*10; i += 256) {
        int ci = i / 660, rem = i % 660;
        int yy = rem / 10, xx = rem % 10;
        int y = y0 + yy - 1, xc = xx - 1;
        float v = 0.f;
        if (y >= 0 && y < 256 && xc >= 0 && xc < 8)
            v = x[(((size_t)(b*C + ci)*L + l)*256 + y)*8 + xc];
        xt[i] = v;
    }
    __syncthreads();

    const int yb = tid >> 3, w = tid & 7;
    float acc[2][24];
    #pragma unroll
    for (int r = 0; r < 2; r++)
        #pragma unroll
        for (int o = 0; o < 24; o++) acc[r][o] = 0.f;

    for (int ci = 0; ci < 8; ci++) {
        float xv[2][9];
        #pragma unroll
        for (int r = 0; r < 2; r++)
            #pragma unroll
            for (int ky = 0; ky < 3; ky++)
                #pragma unroll
                for (int kx = 0; kx < 3; kx++)
                    xv[r][ky*3 + kx] = xt[ci*660 + (yb + r*32 + ky)*10 + (w + kx)];
        #pragma unroll
        for (int o = 0; o < 24; o++) {
            int p = o >> 3, co = o & 7;
            const float* wp = &wsm[p*576 + (co*8 + ci)*9];
            #pragma unroll
            for (int k9 = 0; k9 < 9; k9++) {
                float ww = wp[k9];
                acc[0][o] += xv[0][k9] * ww;
                acc[1][o] += xv[1][k9] * ww;
            }
        }
    }
    #pragma unroll
    for (int p = 0; p < 3; p++) {
        hf* oh = (p == 0) ? g_c0 : (p == 1) ? g_c1 : g_c2;
        #pragma unroll
        for (int co = 0; co < 8; co++)
            #pragma unroll
            for (int r = 0; r < 2; r++) {
                size_t off = (size_t)n*16384 + co*2048 + (size_t)(y0 + yb + r*32)*8 + w;
                oh[off] = __float2half_rn(acc[r][p*8 + co]);
            }
    }
}

// ============================================================
// qkv_wm: transposed proj. K=64 chunks, 2-stage. RoPE fused.
// grid (64, 2, 24), block 256, 2 CTAs/SM.
// ============================================================
#define QKV_SMEM 108544
__global__ void __launch_bounds__(256, 2)
qkv_wm() {
    extern __shared__ __align__(16) char smem[];
    const uint32_t sb = s2u(smem);
    const int tid = threadIdx.x, wid = tid >> 5;
    const int wm = wid >> 1, wn = wid & 1;
    const int c = blockIdx.z & 7, proj = blockIdx.z >> 3;
    const int m0 = blockIdx.x * 128, g0 = blockIdx.y * 128, n0 = m0 >> 3;
    const hf* Ac  = (proj == 0) ? g_c0 : (proj == 1) ? g_c1 : g_c2;
    const hf* Wh_g = g_wh + (size_t)proj * 524288;
    const hf* Wl_g = g_wl + (size_t)proj * 524288;

    DECL_ACC();

    #define QKVLD(s, kc) { \
        uint32_t sbase = sb + (s) * 54272; int k0 = (kc) * 64; \
        _Pragma("unroll") for (int i = 0; i < 4; i++) { \
            int ch = tid + i * 256; \
            int gr = ch >> 3, c8 = ch & 7; \
            size_t gb = (size_t)c * 65536 + (size_t)(g0 + gr) * 256 + k0 + c8 * 8; \
            cpa16(sbase + gr * 144 + c8 * 16,         Wh_g + gb); \
            cpa16(sbase + 18432 + gr * 144 + c8 * 16, Wl_g + gb); \
            int hr = ch & 63, nl = ch >> 6; \
            size_t ga = (size_t)(n0 + nl) * 16384 + c * 2048 + (size_t)(k0 + hr) * 8; \
            cpa16(sbase + 36864 + hr * 272 + nl * 16, Ac + ga); \
        } }

    QKVLD(0, 0); CPCOMMIT();
    for (int kc = 0; kc < 4; kc++) {
        CPWAIT(); __syncthreads();
        if (kc < 3) { QKVLD((kc + 1) & 1, kc + 1); CPCOMMIT(); }
        mma2_rArB(smem + (kc & 1) * 54272, wm, wn, acc);
    }

    EPI_TO_CS();
    const float* Cs = (const float*)smem;
    #pragma unroll
    for (int it = 0; it < 8; it++) {
        int p = tid + it * 256;
        int nl = p >> 7, gr = p & 127;
        const float* src = Cs + gr * 132 + nl * 8;
        float4 v01 = *(const float4*)(src);
        float4 v23 = *(const float4*)(src + 4);
        float v[8] = {v01.x, v01.y, v01.z, v01.w, v23.x, v23.y, v23.z, v23.w};
        int g = g0 + gr;
        if (proj < 2 && (g & 31) < 4) {        // fused RoPE
            int l = (n0 + nl) & 511;
            int jb = (g & 31) * 4;
            #pragma unroll
            for (int t = 0; t < 4; t++) {
                float invf = exp2f(-(float)(jb + t) * (13.287712379549449f / 16.0f));
                float sn, cn;
                sincosf((float)l * invf, &sn, &cn);
                float a = v[2*t], bq = v[2*t+1];
                v[2*t]   = a * cn - bq * sn;
                v[2*t+1] = bq * cn + a * sn;
            }
        }
        size_t e = (size_t)(n0 + nl) * 16384 + (size_t)c * 2048 + (size_t)g * 8;
        if (proj == 0) {
            uint4 H, Lo;
            pack8hl(v, H, Lo);
            *(uint4*)(g_qh + e) = H;
            *(uint4*)(g_ql + e) = Lo;
        } else {
            uint4 H;
            pack8h(v, H);
            *(uint4*)(((proj == 1) ? g_k : g_v) + e) = H;
        }
    }
}

// ============================================================
// qk_wm: K=64 chunks, 2-stage. Epilogue: qk f32 + P hi/lo + sums.
// grid (4, 4, 128), block 256, 2 CTAs/SM.
// ============================================================
#define QK_SMEM 110592
__global__ void __launch_bounds__(256, 2)
qk_wm(const float* __restrict__ prev, float* __restrict__ qk) {
    extern __shared__ __align__(16) char smem[];
    const uint32_t sb = s2u(smem);
    const int tid = threadIdx.x, wid = tid >> 5;
    const int wm = wid >> 1, wn = wid & 1;
    const int z = blockIdx.z;
    const int b = z >> 6, c = (z >> 3) & 7, nh = z & 7;
    const int l0 = blockIdx.y * 128, m0 = blockIdx.x * 128;
    const size_t coff = (size_t)c * 2048 + nh * 256;
    const size_t bL = (size_t)b * 512;

    DECL_ACC();

    #define QKLD(s, kc) { \
        uint32_t sbase = sb + (s) * 55296; int k0 = (kc) * 64; \
        _Pragma("unroll") for (int i = 0; i < 4; i++) { \
            int ch = tid + i * 256; \
            int r = ch >> 3, c8 = ch & 7; \
            uint32_t so = r * 144 + c8 * 16; \
            size_t ga = (bL + l0 + r) * 16384 + coff + k0 + c8 * 8; \
            size_t gb = (bL + m0 + r) * 16384 + coff + k0 + c8 * 8; \
            cpa16(sbase + so,         g_qh + ga); \
            cpa16(sbase + 18432 + so, g_ql + ga); \
            cpa16(sbase + 36864 + so, g_k + gb); \
        } }

    QKLD(0, 0); CPCOMMIT();
    for (int kc = 0; kc < 4; kc++) {
        CPWAIT(); __syncthreads();
        if (kc < 3) { QKLD((kc + 1) & 1, kc + 1); CPCOMMIT(); }
        mma2_rAcB(smem + (kc & 1) * 55296, wm, wn, acc);
    }

    EPI_TO_CS();
    const float* Cs = (const float*)smem;
    const int col4 = (tid & 31) * 4;
    const int rb = tid >> 5;
    const int lane = tid & 31;
    #pragma unroll 4
    for (int jj = 0; jj < 16; jj++) {
        int r = rb + jj * 8;
        float4 cv = *(const float4*)(Cs + r * 132 + col4);
        size_t idx = (size_t)z * LL + (size_t)(l0 + r) * 512 + m0 + col4;
        float4 pv = *(const float4*)(prev + idx);
        float4 o;
        o.x = cv.x * 0.0625f + pv.x;
        o.y = cv.y * 0.0625f + pv.y;
        o.z = cv.z * 0.0625f + pv.z;
        o.w = cv.w * 0.0625f + pv.w;
        *(float4*)(qk + idx) = o;
        float e0 = __expf(o.x), e1 = __expf(o.y);
        float e2 = __expf(o.z), e3 = __expf(o.w);
        hf h0, lo0, h1, lo1, h2, lo2, h3, lo3;
        hsplit(e0, h0, lo0); hsplit(e1, h1, lo1);
        hsplit(e2, h2, lo2); hsplit(e3, h3, lo3);
        *(uint2*)(g_ph + idx) = make_uint2(packh2(h0, h1), packh2(h2, h3));
        *(uint2*)(g_pl + idx) = make_uint2(packh2(lo0, lo1), packh2(lo2, lo3));
        float s = e0 + e1 + e2 + e3;
        #pragma unroll
        for (int off = 16; off; off >>= 1) s += __shfl_xor_sync(~0u, s, off);
        if (lane == 0) atomicAdd(&g_rsum[z * 512 + l0 + r], s);
    }
}

// ============================================================
// pv_wm: K=64 chunks (8), 2-stage. A = P hi/lo, B = V single.
// grid (2, 4, 128), block 256, 2 CTAs/SM.
// ============================================================
#define PV_SMEM 109056
__global__ void __launch_bounds__(256, 2)
pv_wm() {
    extern __shared__ __align__(16) char smem[];
    const uint32_t sb = s2u(smem);
    const int tid = threadIdx.x, wid = tid >> 5;
    const int wm = wid >> 1, wn = wid & 1;
    const int z = blockIdx.z;
    const int b = z >> 6, c = (z >> 3) & 7, nh = z & 7;
    const int l0 = blockIdx.y * 128, d0 = blockIdx.x * 128;
    const size_t coff = (size_t)c * 2048 + nh * 256;
    const size_t bL = (size_t)b * 512;
    float* rinv = (float*)(smem + 108544);
    if (tid < 128) rinv[tid] = 1.0f / g_rsum[z * 512 + l0 + tid];

    DECL_ACC();

    #define PVLD(s, kc) { \
        uint32_t sbase = sb + (s) * 54272; int k0 = (kc) * 64; \
        _Pragma("unroll") for (int i = 0; i < 4; i++) { \
            int ch = tid + i * 256; \
            int r = ch >> 3, c8 = ch & 7; \
            size_t gp = (size_t)z * LL + (size_t)(l0 + r) * 512 + k0 + c8 * 8; \
            cpa16(sbase + r * 144 + c8 * 16,         g_ph + gp); \
            cpa16(sbase + 18432 + r * 144 + c8 * 16, g_pl + gp); \
            int mr = ch >> 4, d8 = ch & 15; \
            size_t gv = (bL + k0 + mr) * 16384 + coff + d0 + d8 * 8; \
            cpa16(sbase + 36864 + mr * 272 + d8 * 16, g_v + gv); \
        } }

    PVLD(0, 0); CPCOMMIT();
    for (int kc = 0; kc < 8; kc++) {
        CPWAIT(); __syncthreads();
        if (kc < 7) { PVLD((kc + 1) & 1, kc + 1); CPCOMMIT(); }
        mma2_rArB(smem + (kc & 1) * 54272, wm, wn, acc);
    }

    EPI_TO_CS();
    const float* Cs = (const float*)smem;
    #pragma unroll
    for (int it = 0; it < 8; it++) {
        int r = (tid >> 4) + it * 16;
        int col8 = (tid & 15) * 8;
        float4 a1 = *(const float4*)(Cs + r * 132 + col8);
        float4 a2 = *(const float4*)(Cs + r * 132 + col8 + 4);
        float iv = rinv[r];
        float v[8] = {a1.x*iv, a1.y*iv, a1.z*iv, a1.w*iv, a2.x*iv, a2.y*iv, a2.z*iv, a2.w*iv};
        uint4 H;
        pack8h(v, H);
        size_t e = (bL + l0 + r) * 16384 + coff + d0 + col8;
        *(uint4*)(g_a + e) = H;
    }
}

// ============================================================
// olin_wm: wo proj, K=64 chunks, 2-stage. -> f32 out.
// grid (64, 2, 8), block 256, 2 CTAs/SM.
// ============================================================
__global__ void __launch_bounds__(256, 2)
olin_wm(float* __restrict__ out) {
    extern __shared__ __align__(16) char smem[];
    const uint32_t sb = s2u(smem);
    const int tid = threadIdx.x, wid = tid >> 5;
    const int wm = wid >> 1, wn = wid & 1;
    const int c = blockIdx.z, m0 = blockIdx.x * 128, g0 = blockIdx.y * 128, n0 = m0 >> 3;
    const hf* Wh_g = g_wh + (size_t)3 * 524288;
    const hf* Wl_g = g_wl + (size_t)3 * 524288;

    DECL_ACC();

    #define OLD(s, kc) { \
        uint32_t sbase = sb + (s) * 54272; int k0 = (kc) * 64; \
        _Pragma("unroll") for (int i = 0; i < 4; i++) { \
            int ch = tid + i * 256; \
            int gr = ch >> 3, c8 = ch & 7; \
            size_t gb = (size_t)c * 65536 + (size_t)(g0 + gr) * 256 + k0 + c8 * 8; \
            cpa16(sbase + gr * 144 + c8 * 16,         Wh_g + gb); \
            cpa16(sbase + 18432 + gr * 144 + c8 * 16, Wl_g + gb); \
            int hr = ch & 63, nl = ch >> 6; \
            size_t ga = (size_t)(n0 + nl) * 16384 + c * 2048 + (size_t)(k0 + hr) * 8; \
            cpa16(sbase + 36864 + hr * 272 + nl * 16, g_a + ga); \
        } }

    OLD(0, 0); CPCOMMIT();
    for (int kc = 0; kc < 4; kc++) {
        CPWAIT(); __syncthreads();
        if (kc < 3) { OLD((kc + 1) & 1, kc + 1); CPCOMMIT(); }
        mma2_rArB(smem + (kc & 1) * 54272, wm, wn, acc);
    }

    EPI_TO_CS();
    const float* Cs = (const float*)smem;
    #pragma unroll
    for (int it = 0; it < 8; it++) {
        int p = tid + it * 256;
        int nl = p >> 7, gr = p & 127;
        int n = n0 + nl, bb = n >> 9, l = n & 511;
        float4 o1 = *(const float4*)(Cs + gr * 132 + nl * 8);
        float4 o2 = *(const float4*)(Cs + gr * 132 + nl * 8 + 4);
        size_t e = ((size_t)(bb * 8 + c) * 512 + l) * 2048 + (size_t)(g0 + gr) * 8;
        *(float4*)(out + e)     = o1;
        *(float4*)(out + e + 4) = o2;
    }
}

// ============================================================
extern "C" void kernel_launch(void* const* d_in, const int* in_sizes, int n_in,
                              void* d_out, int out_size) {
    const float* x    = (const float*)d_in[0];
    const float* prev = (const float*)d_in[1];
    const float* cw_q = (const float*)d_in[2];
    const float* cw_k = (const float*)d_in[3];
    const float* cw_v = (const float*)d_in[4];
    const float* wq   = (const float*)d_in[5];
    const float* wk   = (const float*)d_in[6];
    const float* wv   = (const float*)d_in[7];
    const float* wo   = (const float*)d_in[8];
    float* out    = (float*)d_out;
    float* qk_out = out + (size_t)NCF;

    cudaFuncSetAttribute(qkv_wm,  cudaFuncAttributeMaxDynamicSharedMemorySize, QKV_SMEM);
    cudaFuncSetAttribute(olin_wm, cudaFuncAttributeMaxDynamicSharedMemorySize, QKV_SMEM);
    cudaFuncSetAttribute(qk_wm,   cudaFuncAttributeMaxDynamicSharedMemorySize, QK_SMEM);
    cudaFuncSetAttribute(pv_wm,   cudaFuncAttributeMaxDynamicSharedMemorySize, PV_SMEM);

    conv3_kernel<<<dim3(3072, 4), 256>>>(x, cw_q, cw_k, cw_v, wq, wk, wv, wo);
    qkv_wm<<<dim3(64, 2, 24), 256, QKV_SMEM>>>();
    qk_wm<<<dim3(4, 4, 128), 256, QK_SMEM>>>(prev, qk_out);
    pv_wm<<<dim3(2, 4, 128), 256, PV_SMEM>>>();
    olin_wm<<<dim3(64, 2, 8), 256, QKV_SMEM>>>(out);
}